// round 1
// baseline (speedup 1.0000x reference)
#include <cuda_runtime.h>
#include <cuda_bf16.h>
#include <math.h>

// Problem constants
#define BB   64
#define NN   1024
#define DD   256
#define HH   256
#define G3   768            // 3*H
#define NB   (BB*NN)        // 65536 rows
#define TG   16             // rows per CTA group in GEMM kernels
#define SEQ_CTAS 148

// ---------------- scratch (device globals; no allocation allowed) -------------
__device__ float g_x   [NB*DD];      // node_type_embed rows      (64 MB)
__device__ float g_gi  [NB*G3];      // precomputed input gates   (192 MB)
__device__ float g_h   [NB*HH];      // hidden states, row=(b<<10)|i (64 MB)
__device__ float g_wih_t[DD*G3];     // w_ih transposed: [k][col]
__device__ float g_whh_t[HH*G3];     // w_hh transposed: [k][col]
__device__ unsigned short g_depth[NB];
__device__ int   g_cnt    [BB*NN];   // per (b, level) counts
__device__ int   g_rbstart[BB*NN];   // per (b, level) start offset in g_sched
__device__ int   g_rptr   [NN+1];    // global level boundaries
__device__ int   g_sched  [NB];      // nodes packed (b<<10)|i, sorted by depth
__device__ int   g_maxd;
__device__ unsigned g_bar_count = 0;
__device__ unsigned g_bar_gen   = 0;

// ---------------- prep: transpose weights, reset maxd ------------------------
__global__ void prep_kernel(const float* __restrict__ wih,
                            const float* __restrict__ whh) {
    int idx = blockIdx.x * blockDim.x + threadIdx.x;
    if (idx == 0) g_maxd = 0;
    int total = DD * G3;
    for (int e = idx; e < total; e += gridDim.x * blockDim.x) {
        int k = e / G3, col = e % G3;          // output [k][col]
        g_wih_t[e] = wih[col * DD + k];
        g_whh_t[e] = whh[col * HH + k];
    }
}

// ---------------- embeddings + first half of output ---------------------------
__global__ void embed_kernel(const int* __restrict__ node_types,
                             const int* __restrict__ node_vals,
                             const int* __restrict__ child_positions,
                             const float* __restrict__ type_emb,
                             const float* __restrict__ pos_table,
                             const float* __restrict__ token_emb,
                             float* __restrict__ out) {
    int id  = blockIdx.x;            // 0..NB-1 ; b = id>>10, n = id&1023
    int tid = threadIdx.x;           // 0..255 = d
    int b = id >> 10, n = id & 1023;
    int tt = node_types[id];
    int cp = child_positions[id];
    int v0 = node_vals[2*id];
    int v1 = node_vals[2*id + 1];
    float x = type_emb[tt*DD + tid] * 4.0f + pos_table[cp*DD + tid] * 0.25f;
    float tok = token_emb[v0*DD + tid] + token_emb[v1*DD + tid];
    g_x[id*DD + tid] = x;
    // out[n, b, d] ; token mean (/2) * SCALE(4) => *2
    out[((n*BB + b) * (DD+HH)) + tid] = x + tok * 2.0f;
}

// ---------------- GI GEMM: g_gi[row] = g_x[row] @ w_ih^T + b_ih ---------------
__global__ void __launch_bounds__(256) gi_kernel(const float* __restrict__ bih) {
    __shared__ float sA[TG][DD];
    int tid  = threadIdx.x;          // = output col j in [0,256)
    int row0 = blockIdx.x * TG;
    // stage TG activation rows
    for (int idx = tid; idx < TG*DD/4; idx += 256) {
        ((float4*)&sA[0][0])[idx] = ((const float4*)&g_x[row0*DD])[idx];
    }
    __syncthreads();
    float ar[TG], az[TG], an[TG];
    #pragma unroll
    for (int t = 0; t < TG; t++) { ar[t]=0.f; az[t]=0.f; an[t]=0.f; }
    #pragma unroll 1
    for (int k = 0; k < DD; k += 4) {
        const float* wp = g_wih_t + k*G3 + tid;
        float wr0=wp[0],    wz0=wp[256],  wn0=wp[512];
        float wr1=wp[768],  wz1=wp[1024], wn1=wp[1280];
        float wr2=wp[1536], wz2=wp[1792], wn2=wp[2048];
        float wr3=wp[2304], wz3=wp[2560], wn3=wp[2816];
        #pragma unroll
        for (int t = 0; t < TG; t++) {
            float4 a = *(const float4*)(&sA[t][k]);
            ar[t]=fmaf(a.x,wr0,ar[t]); az[t]=fmaf(a.x,wz0,az[t]); an[t]=fmaf(a.x,wn0,an[t]);
            ar[t]=fmaf(a.y,wr1,ar[t]); az[t]=fmaf(a.y,wz1,az[t]); an[t]=fmaf(a.y,wn1,an[t]);
            ar[t]=fmaf(a.z,wr2,ar[t]); az[t]=fmaf(a.z,wz2,az[t]); an[t]=fmaf(a.z,wn2,an[t]);
            ar[t]=fmaf(a.w,wr3,ar[t]); az[t]=fmaf(a.w,wz3,az[t]); an[t]=fmaf(a.w,wn3,an[t]);
        }
    }
    float br = bih[tid], bz = bih[tid+256], bn = bih[tid+512];
    #pragma unroll
    for (int t = 0; t < TG; t++) {
        float* gp = g_gi + (long)(row0 + t) * G3;
        gp[tid]       = ar[t] + br;
        gp[tid + 256] = az[t] + bz;
        gp[tid + 512] = an[t] + bn;
    }
}

// ---------------- scheduler S1: depths + per-b level counts -------------------
__global__ void sched1_kernel(const int* __restrict__ lpi) {
    __shared__ int            slpi[NN];
    __shared__ unsigned short sdep[NN];
    __shared__ int            scnt[NN];
    int b = blockIdx.x, tid = threadIdx.x;
    for (int i = tid; i < NN; i += blockDim.x) { slpi[i] = lpi[b*NN + i]; scnt[i] = 0; }
    __syncthreads();
    if (tid == 0) {
        int maxd = 0;
        sdep[0] = 0; scnt[0] = 1;
        for (int i = 1; i < NN; i++) {
            int d = sdep[slpi[i]] + 1;
            sdep[i] = (unsigned short)d;
            scnt[d]++;
            if (d > maxd) maxd = d;
        }
        atomicMax(&g_maxd, maxd);
    }
    __syncthreads();
    for (int i = tid; i < NN; i += blockDim.x) {
        g_depth[b*NN + i] = sdep[i];
        g_cnt  [b*NN + i] = scnt[i];
    }
}

// ---------------- scheduler S2: global level prefix + per-(b,level) starts ----
__global__ void __launch_bounds__(1024) sched2_kernel() {
    __shared__ int stot[NN];
    __shared__ int srptr[NN+1];
    int r = threadIdx.x;   // 0..1023
    int s = 0;
    for (int b = 0; b < BB; b++) {
        g_rbstart[b*NN + r] = s;      // partial (add srptr[r] later)
        s += g_cnt[b*NN + r];
    }
    stot[r] = s;
    __syncthreads();
    if (r == 0) {
        int acc = 0;
        for (int i = 0; i < NN; i++) { srptr[i] = acc; acc += stot[i]; }
        srptr[NN] = acc;
    }
    __syncthreads();
    for (int b = 0; b < BB; b++) g_rbstart[b*NN + r] += srptr[r];
    g_rptr[r] = srptr[r];
    if (r == 0) g_rptr[NN] = srptr[NN];
}

// ---------------- scheduler S3: scatter into depth-sorted schedule ------------
__global__ void sched3_kernel() {
    __shared__ int            scur[NN];
    __shared__ unsigned short sdep[NN];
    int b = blockIdx.x, tid = threadIdx.x;
    for (int i = tid; i < NN; i += blockDim.x) {
        scur[i] = g_rbstart[b*NN + i];
        sdep[i] = g_depth  [b*NN + i];
    }
    __syncthreads();
    if (tid == 0) {
        for (int i = 0; i < NN; i++) {
            int r = sdep[i];
            g_sched[scur[r]++] = (b << 10) | i;
        }
    }
}

// ---------------- persistent GRU kernel (level-parallel) ----------------------
__device__ __forceinline__ void grid_barrier() {
    __threadfence();
    __syncthreads();
    if (threadIdx.x == 0) {
        unsigned gen = *(volatile unsigned*)&g_bar_gen;
        if (atomicAdd(&g_bar_count, 1u) == (unsigned)gridDim.x - 1u) {
            g_bar_count = 0u;
            __threadfence();
            *(volatile unsigned*)&g_bar_gen = gen + 1u;
        } else {
            while (*(volatile unsigned*)&g_bar_gen == gen) { }
        }
        __threadfence();
    }
    __syncthreads();
}

__device__ __forceinline__ float sigm(float x) { return 1.0f / (1.0f + expf(-x)); }

__global__ void __launch_bounds__(256) seq_kernel(const int* __restrict__ lpi,
                                                  const float* __restrict__ bhh,
                                                  float* __restrict__ out) {
    __shared__ float sP[TG][DD];
    __shared__ int   sMeta[TG];
    __shared__ int   sPar[TG];
    int tid = threadIdx.x;
    float bhr = bhh[tid], bhz = bhh[tid+256], bhn = bhh[tid+512];
    int maxd = g_maxd;

    for (int r = 0; r <= maxd; r++) {
        int start = g_rptr[r];
        int cnt   = g_rptr[r+1] - start;
        int ngroups = (cnt + TG - 1) / TG;
        for (int g = blockIdx.x; g < ngroups; g += gridDim.x) {
            int t0 = start + g * TG;
            int tc = cnt - g * TG; if (tc > TG) tc = TG;
            if (tid < tc) {
                int s = g_sched[t0 + tid];
                sMeta[tid] = s;
                int b = s >> 10, i = s & 1023;
                sPar[tid] = (i == 0) ? -1 : ((b << 10) | lpi[b*NN + i]);
            }
            __syncthreads();
            // gather parent hidden rows (float4 vectorized)
            for (int idx = tid; idx < tc * (DD/4); idx += 256) {
                int t = idx >> 6, k4 = idx & 63;
                int pr = sPar[t];
                float4 v;
                if (pr < 0) { v.x=v.y=v.z=v.w=0.f; }
                else        { v = ((const float4*)&g_h[(long)pr*HH])[k4]; }
                ((float4*)&sP[t][0])[k4] = v;
            }
            __syncthreads();
            float ar[TG], az[TG], an[TG];
            #pragma unroll
            for (int t = 0; t < TG; t++) { ar[t]=0.f; az[t]=0.f; an[t]=0.f; }
            #pragma unroll 1
            for (int k = 0; k < HH; k += 4) {
                const float* wp = g_whh_t + k*G3 + tid;
                float wr0=wp[0],    wz0=wp[256],  wn0=wp[512];
                float wr1=wp[768],  wz1=wp[1024], wn1=wp[1280];
                float wr2=wp[1536], wz2=wp[1792], wn2=wp[2048];
                float wr3=wp[2304], wz3=wp[2560], wn3=wp[2816];
                #pragma unroll
                for (int t = 0; t < TG; t++) {
                    float4 a = *(const float4*)(&sP[t][k]);
                    ar[t]=fmaf(a.x,wr0,ar[t]); az[t]=fmaf(a.x,wz0,az[t]); an[t]=fmaf(a.x,wn0,an[t]);
                    ar[t]=fmaf(a.y,wr1,ar[t]); az[t]=fmaf(a.y,wz1,az[t]); an[t]=fmaf(a.y,wn1,an[t]);
                    ar[t]=fmaf(a.z,wr2,ar[t]); az[t]=fmaf(a.z,wz2,az[t]); an[t]=fmaf(a.z,wn2,an[t]);
                    ar[t]=fmaf(a.w,wr3,ar[t]); az[t]=fmaf(a.w,wz3,az[t]); an[t]=fmaf(a.w,wn3,an[t]);
                }
            }
            for (int t = 0; t < tc; t++) {
                int s = sMeta[t];
                int b = s >> 10, i = s & 1023;
                long row = (long)s;                    // (b<<10)|i == b*1024+i
                const float* gp = g_gi + row * G3;
                float gir = gp[tid], giz = gp[tid+256], gin = gp[tid+512];
                float rg = sigm(gir + ar[t] + bhr);
                float zg = sigm(giz + az[t] + bhz);
                float ng = tanhf(gin + (an[t] + bhn) * rg);
                float pv = sP[t][tid];
                float h  = (1.0f - zg) * ng + zg * pv;
                g_h[row * HH + tid] = h;
                out[((long)(i*BB + b) * (DD+HH)) + DD + tid] = h;
            }
            __syncthreads();
        }
        grid_barrier();
    }
}

// ---------------- launch ------------------------------------------------------
extern "C" void kernel_launch(void* const* d_in, const int* in_sizes, int n_in,
                              void* d_out, int out_size) {
    const int*   node_types      = (const int*)  d_in[0];
    const int*   node_vals       = (const int*)  d_in[1];
    /* node_val_offsets d_in[2] unused: uniform bags of 2 */
    const int*   last_parent     = (const int*)  d_in[3];
    const int*   child_positions = (const int*)  d_in[4];
    const float* type_emb        = (const float*)d_in[5];
    const float* pos_table       = (const float*)d_in[6];
    const float* token_emb       = (const float*)d_in[7];
    const float* w_ih            = (const float*)d_in[8];
    const float* w_hh            = (const float*)d_in[9];
    const float* b_ih            = (const float*)d_in[10];
    const float* b_hh            = (const float*)d_in[11];
    float* out = (float*)d_out;

    prep_kernel<<<192, 256>>>(w_ih, w_hh);
    embed_kernel<<<NB, 256>>>(node_types, node_vals, child_positions,
                              type_emb, pos_table, token_emb, out);
    gi_kernel<<<NB/TG, 256>>>(b_ih);
    sched1_kernel<<<BB, 256>>>(last_parent);
    sched2_kernel<<<1, 1024>>>();
    sched3_kernel<<<BB, 256>>>();
    seq_kernel<<<SEQ_CTAS, 256>>>(last_parent, b_hh, out);
}

// round 3
// speedup vs baseline: 1.9997x; 1.9997x over previous
#include <cuda_runtime.h>
#include <cuda_bf16.h>
#include <math.h>
#include <stdint.h>

// Problem constants
#define BB   64
#define NN   1024
#define DD   256
#define HH   256
#define G3   768            // 3*H
#define NB   (BB*NN)        // 65536 rows
#define TG   32             // rows per group in seq kernel
#define SEQ_CTAS 148
#define PITCH 264           // bf16 pitch for A smem tiles (conflict-free frags)

// ---------------- scratch (device globals) ------------------------------------
__device__ float g_gi  [NB*G3];                 // input gates (192 MB)
__device__ float g_h   [NB*HH];                 // hidden states (64 MB)
__device__ __nv_bfloat16 g_x_hi[NB*DD];
__device__ __nv_bfloat16 g_x_lo[NB*DD];
__device__ __nv_bfloat16 g_wih_hi[G3*DD];       // [n][k] k-contiguous
__device__ __nv_bfloat16 g_wih_lo[G3*DD];
__device__ __nv_bfloat16 g_whh_hi[G3*HH];
__device__ __nv_bfloat16 g_whh_lo[G3*HH];
__device__ unsigned short g_depth[NB];
__device__ int   g_cnt    [BB*NN];
__device__ int   g_rbstart[BB*NN];
__device__ int   g_rptr   [NN+1];
__device__ int   g_sched  [NB];
__device__ int   g_maxd;
__device__ unsigned g_bar_count = 0;
__device__ unsigned g_bar_gen   = 0;

// ---------------- helpers ------------------------------------------------------
__device__ __forceinline__ void mma16816(float* c,
        uint32_t a0, uint32_t a1, uint32_t a2, uint32_t a3,
        uint32_t b0, uint32_t b1) {
    asm volatile("mma.sync.aligned.m16n8k16.row.col.f32.bf16.bf16.f32 "
        "{%0,%1,%2,%3}, {%4,%5,%6,%7}, {%8,%9}, {%0,%1,%2,%3};"
        : "+f"(c[0]), "+f"(c[1]), "+f"(c[2]), "+f"(c[3])
        : "r"(a0), "r"(a1), "r"(a2), "r"(a3), "r"(b0), "r"(b1));
}
__device__ __forceinline__ float2 unpack_b2(uint32_t v) {
    __nv_bfloat162 h = *reinterpret_cast<__nv_bfloat162*>(&v);
    return make_float2(__bfloat162float(h.x), __bfloat162float(h.y));
}
__device__ __forceinline__ uint32_t pack_b2(float x, float y) {
    __nv_bfloat162 h = __floats2bfloat162_rn(x, y);
    return *reinterpret_cast<uint32_t*>(&h);
}
__device__ __forceinline__ float sigm(float x) { return 1.0f / (1.0f + expf(-x)); }

// ---------------- prep: split weights into bf16 hi/lo --------------------------
__global__ void prep_kernel(const float* __restrict__ wih,
                            const float* __restrict__ whh) {
    int idx = blockIdx.x * blockDim.x + threadIdx.x;
    if (idx == 0) g_maxd = 0;
    int total = G3 * DD;
    for (int e = idx; e < total; e += gridDim.x * blockDim.x) {
        float wi = wih[e];
        __nv_bfloat16 hi = __float2bfloat16(wi);
        g_wih_hi[e] = hi;
        g_wih_lo[e] = __float2bfloat16(wi - __bfloat162float(hi));
        float wh = whh[e];
        __nv_bfloat16 hh = __float2bfloat16(wh);
        g_whh_hi[e] = hh;
        g_whh_lo[e] = __float2bfloat16(wh - __bfloat162float(hh));
    }
}

// ---------------- embeddings + first half of output ----------------------------
__global__ void embed_kernel(const int* __restrict__ node_types,
                             const int* __restrict__ node_vals,
                             const int* __restrict__ child_positions,
                             const float* __restrict__ type_emb,
                             const float* __restrict__ pos_table,
                             const float* __restrict__ token_emb,
                             float* __restrict__ out) {
    int id  = blockIdx.x;
    int tid = threadIdx.x;
    int b = id >> 10, n = id & 1023;
    int tt = node_types[id];
    int cp = child_positions[id];
    int v0 = node_vals[2*id];
    int v1 = node_vals[2*id + 1];
    float x = type_emb[tt*DD + tid] * 4.0f + pos_table[cp*DD + tid] * 0.25f;
    float tok = token_emb[v0*DD + tid] + token_emb[v1*DD + tid];
    __nv_bfloat16 hi = __float2bfloat16(x);
    __nv_bfloat16 lo = __float2bfloat16(x - __bfloat162float(hi));
    g_x_hi[id*DD + tid] = hi;
    g_x_lo[id*DD + tid] = lo;
    out[((n*BB + b) * (DD+HH)) + tid] = x + tok * 2.0f;
}

// ---------------- GI GEMM via mma.sync (M64 per CTA, 3 N-chunks of 256) --------
// warp grid 2x4: wm=wid>>2 (m half), wc=wid&3 (64-col slice)
#define GI_SMEM (2 * 64 * PITCH * 2)   // hi+lo A tiles, bytes

__global__ void __launch_bounds__(256, 1) gi_mma_kernel(const float* __restrict__ bih) {
    extern __shared__ __nv_bfloat16 sA[];       // [2][64][PITCH]
    __nv_bfloat16* sHi = sA;
    __nv_bfloat16* sLo = sA + 64 * PITCH;
    int tid = threadIdx.x;
    int wid = tid >> 5, lane = tid & 31;
    int gid = lane >> 2, tq = lane & 3;
    int wm = wid >> 2, wc = wid & 3;
    long row0 = (long)blockIdx.x * 64;

    // fill A: 64 rows x 128 u32 per precision
    {
        const uint32_t* srcH = (const uint32_t*)g_x_hi + row0 * 128;
        const uint32_t* srcL = (const uint32_t*)g_x_lo + row0 * 128;
        uint32_t* dH = (uint32_t*)sHi;
        uint32_t* dL = (uint32_t*)sLo;
        for (int idx = tid; idx < 64 * 128; idx += 256) {
            int m = idx >> 7, j = idx & 127;
            dH[m * (PITCH/2) + j] = srcH[idx];
            dL[m * (PITCH/2) + j] = srcL[idx];
        }
    }
    __syncthreads();

    const uint32_t* pH = (const uint32_t*)sHi;
    const uint32_t* pL = (const uint32_t*)sLo;
    const uint32_t* wH = (const uint32_t*)g_wih_hi;
    const uint32_t* wL = (const uint32_t*)g_wih_lo;

    for (int c = 0; c < 3; c++) {
        float C[2][8][4];
        #pragma unroll
        for (int mt = 0; mt < 2; mt++)
            #pragma unroll
            for (int nt = 0; nt < 8; nt++)
                #pragma unroll
                for (int q = 0; q < 4; q++) C[mt][nt][q] = 0.0f;

        #pragma unroll 1
        for (int ks = 0; ks < 16; ks++) {
            int kb = ks * 8;
            uint32_t aH[2][4], aL[2][4];
            #pragma unroll
            for (int mt = 0; mt < 2; mt++) {
                int r = wm * 32 + mt * 16 + gid;
                int o = r * (PITCH/2) + kb + tq;
                int o8 = o + 8 * (PITCH/2);
                aH[mt][0] = pH[o];  aH[mt][1] = pH[o8];
                aH[mt][2] = pH[o+4]; aH[mt][3] = pH[o8+4];
                aL[mt][0] = pL[o];  aL[mt][1] = pL[o8];
                aL[mt][2] = pL[o+4]; aL[mt][3] = pL[o8+4];
            }
            #pragma unroll
            for (int nt = 0; nt < 8; nt++) {
                int n = c * 256 + wc * 64 + nt * 8 + gid;
                int bo = n * 128 + kb + tq;
                uint32_t bh0 = wH[bo], bh1 = wH[bo + 4];
                uint32_t bl0 = wL[bo], bl1 = wL[bo + 4];
                #pragma unroll
                for (int mt = 0; mt < 2; mt++) {
                    mma16816(C[mt][nt], aH[mt][0], aH[mt][1], aH[mt][2], aH[mt][3], bh0, bh1);
                    mma16816(C[mt][nt], aL[mt][0], aL[mt][1], aL[mt][2], aL[mt][3], bh0, bh1);
                    mma16816(C[mt][nt], aH[mt][0], aH[mt][1], aH[mt][2], aH[mt][3], bl0, bl1);
                }
            }
        }
        // epilogue: add bias, store fp32
        #pragma unroll
        for (int mt = 0; mt < 2; mt++) {
            long r = row0 + wm * 32 + mt * 16 + gid;
            #pragma unroll
            for (int nt = 0; nt < 8; nt++) {
                int col = c * 256 + wc * 64 + nt * 8 + tq * 2;
                float2 bv = *(const float2*)(bih + col);
                float2 v0 = make_float2(C[mt][nt][0] + bv.x, C[mt][nt][1] + bv.y);
                float2 v1 = make_float2(C[mt][nt][2] + bv.x, C[mt][nt][3] + bv.y);
                *(float2*)(g_gi + r * G3 + col)       = v0;
                *(float2*)(g_gi + (r + 8) * G3 + col) = v1;
            }
        }
    }
}

// ---------------- scheduler S1: depths + per-b level counts --------------------
__global__ void sched1_kernel(const int* __restrict__ lpi) {
    __shared__ int            slpi[NN];
    __shared__ unsigned short sdep[NN];
    __shared__ int            scnt[NN];
    int b = blockIdx.x, tid = threadIdx.x;
    for (int i = tid; i < NN; i += blockDim.x) { slpi[i] = lpi[b*NN + i]; scnt[i] = 0; }
    __syncthreads();
    if (tid == 0) {
        int maxd = 0;
        sdep[0] = 0; scnt[0] = 1;
        for (int i = 1; i < NN; i++) {
            int d = sdep[slpi[i]] + 1;
            sdep[i] = (unsigned short)d;
            scnt[d]++;
            if (d > maxd) maxd = d;
        }
        atomicMax(&g_maxd, maxd);
    }
    __syncthreads();
    for (int i = tid; i < NN; i += blockDim.x) {
        g_depth[b*NN + i] = sdep[i];
        g_cnt  [b*NN + i] = scnt[i];
    }
}

// ---------------- scheduler S2 -------------------------------------------------
__global__ void __launch_bounds__(1024) sched2_kernel() {
    __shared__ int stot[NN];
    __shared__ int srptr[NN+1];
    int r = threadIdx.x;
    int s = 0;
    for (int b = 0; b < BB; b++) {
        g_rbstart[b*NN + r] = s;
        s += g_cnt[b*NN + r];
    }
    stot[r] = s;
    __syncthreads();
    if (r == 0) {
        int acc = 0;
        for (int i = 0; i < NN; i++) { srptr[i] = acc; acc += stot[i]; }
        srptr[NN] = acc;
    }
    __syncthreads();
    for (int b = 0; b < BB; b++) g_rbstart[b*NN + r] += srptr[r];
    g_rptr[r] = srptr[r];
    if (r == 0) g_rptr[NN] = srptr[NN];
}

// ---------------- scheduler S3 -------------------------------------------------
__global__ void sched3_kernel() {
    __shared__ int            scur[NN];
    __shared__ unsigned short sdep[NN];
    int b = blockIdx.x, tid = threadIdx.x;
    for (int i = tid; i < NN; i += blockDim.x) {
        scur[i] = g_rbstart[b*NN + i];
        sdep[i] = g_depth  [b*NN + i];
    }
    __syncthreads();
    if (tid == 0) {
        for (int i = 0; i < NN; i++) {
            int r = sdep[i];
            g_sched[scur[r]++] = (b << 10) | i;
        }
    }
}

// ---------------- persistent level-parallel GRU (mma.sync) ---------------------
__device__ __forceinline__ void grid_barrier() {
    __threadfence();
    __syncthreads();
    if (threadIdx.x == 0) {
        unsigned gen = *(volatile unsigned*)&g_bar_gen;
        if (atomicAdd(&g_bar_count, 1u) == (unsigned)gridDim.x - 1u) {
            g_bar_count = 0u;
            __threadfence();
            *(volatile unsigned*)&g_bar_gen = gen + 1u;
        } else {
            while (*(volatile unsigned*)&g_bar_gen == gen) { }
        }
        __threadfence();
    }
    __syncthreads();
}

// warp wid owns n-tiles {wid + 8*jj : jj=0..11}; triplet (c, c+256, c+512)
// for c in warp's base cols lives in jj, jj+4, jj+8 of the SAME warp.
__global__ void __launch_bounds__(256, 1) seq_kernel(const int* __restrict__ lpi,
                                                     const float* __restrict__ bhh,
                                                     float* __restrict__ out) {
    __shared__ __nv_bfloat16 sHi[TG * PITCH];
    __shared__ __nv_bfloat16 sLo[TG * PITCH];
    __shared__ int sMeta[TG];
    __shared__ int sPar[TG];
    int tid = threadIdx.x;
    int wid = tid >> 5, lane = tid & 31;
    int gid = lane >> 2, tq = lane & 3;
    int maxd = g_maxd;

    const uint32_t* wH = (const uint32_t*)g_whh_hi;
    const uint32_t* wL = (const uint32_t*)g_whh_lo;
    uint32_t* dH = (uint32_t*)sHi;
    uint32_t* dL = (uint32_t*)sLo;

    for (int r = 0; r <= maxd; r++) {
        int start = g_rptr[r];
        int cnt   = g_rptr[r+1] - start;
        int ngroups = (cnt + TG - 1) / TG;
        for (int g = blockIdx.x; g < ngroups; g += gridDim.x) {
            int t0 = start + g * TG;
            int tc = cnt - g * TG; if (tc > TG) tc = TG;
            if (tid < TG) {
                if (tid < tc) {
                    int s = g_sched[t0 + tid];
                    sMeta[tid] = s;
                    int b = s >> 10, i = s & 1023;
                    sPar[tid] = (i == 0) ? -1 : ((b << 10) | lpi[b*NN + i]);
                } else { sMeta[tid] = 0; sPar[tid] = -1; }
            }
            __syncthreads();
            // gather parents -> split bf16 smem
            for (int idx = tid; idx < TG * 64; idx += 256) {
                int t = idx >> 6, k4 = idx & 63;
                int pr = sPar[t];
                float4 v;
                if (pr < 0) { v.x=v.y=v.z=v.w=0.f; }
                else        { v = ((const float4*)&g_h[(long)pr*HH])[k4]; }
                float hx = __bfloat162float(__float2bfloat16(v.x));
                float hy = __bfloat162float(__float2bfloat16(v.y));
                float hz = __bfloat162float(__float2bfloat16(v.z));
                float hw = __bfloat162float(__float2bfloat16(v.w));
                int o = t * (PITCH/2) + k4 * 2;
                dH[o]   = pack_b2(hx, hy);
                dH[o+1] = pack_b2(hz, hw);
                dL[o]   = pack_b2(v.x - hx, v.y - hy);
                dL[o+1] = pack_b2(v.z - hz, v.w - hw);
            }
            __syncthreads();

            float C[2][12][4];
            #pragma unroll
            for (int mt = 0; mt < 2; mt++)
                #pragma unroll
                for (int jj = 0; jj < 12; jj++)
                    #pragma unroll
                    for (int q = 0; q < 4; q++) C[mt][jj][q] = 0.0f;

            const uint32_t* pH = (const uint32_t*)sHi;
            const uint32_t* pL = (const uint32_t*)sLo;
            #pragma unroll 1
            for (int ks = 0; ks < 16; ks++) {
                int kb = ks * 8;
                uint32_t aH[2][4], aL[2][4];
                #pragma unroll
                for (int mt = 0; mt < 2; mt++) {
                    int rr = mt * 16 + gid;
                    int o = rr * (PITCH/2) + kb + tq;
                    int o8 = o + 8 * (PITCH/2);
                    aH[mt][0] = pH[o];  aH[mt][1] = pH[o8];
                    aH[mt][2] = pH[o+4]; aH[mt][3] = pH[o8+4];
                    aL[mt][0] = pL[o];  aL[mt][1] = pL[o8];
                    aL[mt][2] = pL[o+4]; aL[mt][3] = pL[o8+4];
                }
                #pragma unroll
                for (int jj = 0; jj < 12; jj++) {
                    int n = 8 * wid + 64 * jj + gid;
                    int bo = n * 128 + kb + tq;
                    uint32_t bh0 = wH[bo], bh1 = wH[bo + 4];
                    uint32_t bl0 = wL[bo], bl1 = wL[bo + 4];
                    #pragma unroll
                    for (int mt = 0; mt < 2; mt++) {
                        mma16816(C[mt][jj], aH[mt][0], aH[mt][1], aH[mt][2], aH[mt][3], bh0, bh1);
                        mma16816(C[mt][jj], aL[mt][0], aL[mt][1], aL[mt][2], aL[mt][3], bh0, bh1);
                        mma16816(C[mt][jj], aH[mt][0], aH[mt][1], aH[mt][2], aH[mt][3], bl0, bl1);
                    }
                }
            }

            // fused GRU epilogue: warp holds (r,z,n) triplets for its cols
            #pragma unroll
            for (int jj = 0; jj < 4; jj++) {
                int cp = 8 * (wid + 8 * jj) + tq * 2;     // base col in [0,256)
                float2 br = *(const float2*)(bhh + cp);
                float2 bz = *(const float2*)(bhh + 256 + cp);
                float2 bn = *(const float2*)(bhh + 512 + cp);
                #pragma unroll
                for (int mt = 0; mt < 2; mt++) {
                    #pragma unroll
                    for (int rh = 0; rh < 2; rh++) {
                        int lr = mt * 16 + gid + rh * 8;
                        if (lr >= tc) continue;
                        float cr0 = C[mt][jj][rh*2],   cr1 = C[mt][jj][rh*2+1];
                        float cz0 = C[mt][jj+4][rh*2], cz1 = C[mt][jj+4][rh*2+1];
                        float cn0 = C[mt][jj+8][rh*2], cn1 = C[mt][jj+8][rh*2+1];
                        int s = sMeta[lr];
                        long row = (long)s;
                        int b = s >> 10, i = s & 1023;
                        const float* gp = g_gi + row * G3;
                        float2 gr = *(const float2*)(gp + cp);
                        float2 gz = *(const float2*)(gp + 256 + cp);
                        float2 gn = *(const float2*)(gp + 512 + cp);
                        int ho = lr * (PITCH/2) + cp / 2;
                        float2 fh = unpack_b2(((const uint32_t*)sHi)[ho]);
                        float2 fl = unpack_b2(((const uint32_t*)sLo)[ho]);
                        float hp0 = fh.x + fl.x, hp1 = fh.y + fl.y;
                        float rg0 = sigm(gr.x + cr0 + br.x);
                        float rg1 = sigm(gr.y + cr1 + br.y);
                        float zg0 = sigm(gz.x + cz0 + bz.x);
                        float zg1 = sigm(gz.y + cz1 + bz.y);
                        float ng0 = tanhf(gn.x + (cn0 + bn.x) * rg0);
                        float ng1 = tanhf(gn.y + (cn1 + bn.y) * rg1);
                        float h0 = (1.0f - zg0) * ng0 + zg0 * hp0;
                        float h1 = (1.0f - zg1) * ng1 + zg1 * hp1;
                        *(float2*)(g_h + row * HH + cp) = make_float2(h0, h1);
                        *(float2*)(out + ((long)(i*BB + b) * (DD+HH)) + DD + cp) = make_float2(h0, h1);
                    }
                }
            }
            __syncthreads();
        }
        grid_barrier();
    }
}

// ---------------- launch -------------------------------------------------------
extern "C" void kernel_launch(void* const* d_in, const int* in_sizes, int n_in,
                              void* d_out, int out_size) {
    const int*   node_types      = (const int*)  d_in[0];
    const int*   node_vals       = (const int*)  d_in[1];
    const int*   last_parent     = (const int*)  d_in[3];
    const int*   child_positions = (const int*)  d_in[4];
    const float* type_emb        = (const float*)d_in[5];
    const float* pos_table       = (const float*)d_in[6];
    const float* token_emb       = (const float*)d_in[7];
    const float* w_ih            = (const float*)d_in[8];
    const float* w_hh            = (const float*)d_in[9];
    const float* b_ih            = (const float*)d_in[10];
    const float* b_hh            = (const float*)d_in[11];
    float* out = (float*)d_out;

    cudaFuncSetAttribute(gi_mma_kernel, cudaFuncAttributeMaxDynamicSharedMemorySize, GI_SMEM);

    prep_kernel<<<192, 256>>>(w_ih, w_hh);
    embed_kernel<<<NB, 256>>>(node_types, node_vals, child_positions,
                              type_emb, pos_table, token_emb, out);
    gi_mma_kernel<<<NB/64, 256, GI_SMEM>>>(b_ih);
    sched1_kernel<<<BB, 256>>>(last_parent);
    sched2_kernel<<<1, 1024>>>();
    sched3_kernel<<<BB, 256>>>();
    seq_kernel<<<SEQ_CTAS, 256>>>(last_parent, b_hh, out);
}

// round 4
// speedup vs baseline: 3.0465x; 1.5234x over previous
#include <cuda_runtime.h>
#include <cuda_bf16.h>
#include <math.h>
#include <stdint.h>

// Problem constants
#define BB   64
#define NN   1024
#define DD   256
#define HH   256
#define G3   768            // 3*H
#define NB   (BB*NN)        // 65536 rows
#define TG   32             // rows per group in seq kernel
#define SEQ_CTAS 148
#define PITCH 264           // bf16 pitch for A smem tiles (132 u32; LDSM conflict-free)

// ---------------- scratch (device globals) ------------------------------------
__device__ float g_gi  [NB*G3];                 // input gates (192 MB)
__device__ float g_h   [NB*HH];                 // hidden states (64 MB)
__device__ __nv_bfloat16 g_x_hi[NB*DD];
__device__ __nv_bfloat16 g_x_lo[NB*DD];
// frag-packed weights: [n][ks][tq] -> uint4 {hi0, hi1, lo0, lo1}
__device__ __align__(16) uint4 g_wih_p[G3*64];
__device__ __align__(16) uint4 g_whh_p[G3*64];
__device__ unsigned short g_depth[NB];
__device__ int   g_cnt    [BB*NN];
__device__ int   g_rbstart[BB*NN];
__device__ int   g_rptr   [NN+1];
__device__ int   g_sched  [NB];
__device__ int   g_maxd;
__device__ unsigned g_bar_count = 0;
__device__ unsigned g_bar_gen   = 0;

// ---------------- helpers ------------------------------------------------------
__device__ __forceinline__ void mma16816(float* c,
        uint32_t a0, uint32_t a1, uint32_t a2, uint32_t a3,
        uint32_t b0, uint32_t b1) {
    asm volatile("mma.sync.aligned.m16n8k16.row.col.f32.bf16.bf16.f32 "
        "{%0,%1,%2,%3}, {%4,%5,%6,%7}, {%8,%9}, {%0,%1,%2,%3};"
        : "+f"(c[0]), "+f"(c[1]), "+f"(c[2]), "+f"(c[3])
        : "r"(a0), "r"(a1), "r"(a2), "r"(a3), "r"(b0), "r"(b1));
}
__device__ __forceinline__ void ldsm4(uint32_t addr, uint32_t* r) {
    asm volatile("ldmatrix.sync.aligned.m8n8.x4.shared.b16 {%0,%1,%2,%3}, [%4];"
        : "=r"(r[0]), "=r"(r[1]), "=r"(r[2]), "=r"(r[3]) : "r"(addr));
}
__device__ __forceinline__ uint32_t smem_u32(const void* p) {
    uint32_t a;
    asm("{ .reg .u64 t; cvta.to.shared.u64 t, %1; cvt.u32.u64 %0, t; }" : "=r"(a) : "l"(p));
    return a;
}
__device__ __forceinline__ float2 unpack_b2(uint32_t v) {
    __nv_bfloat162 h = *reinterpret_cast<__nv_bfloat162*>(&v);
    return make_float2(__bfloat162float(h.x), __bfloat162float(h.y));
}
__device__ __forceinline__ uint32_t pack_b2(float x, float y) {
    __nv_bfloat162 h = __floats2bfloat162_rn(x, y);
    return *reinterpret_cast<uint32_t*>(&h);
}
__device__ __forceinline__ float sigm(float x) { return 1.0f / (1.0f + expf(-x)); }

// ---------------- prep: frag-pack both weight matrices -------------------------
// pw[n][ks][tq] = {pack(hi(2p),hi(2p+1)), pack(hi(2p+8),hi(2p+9)),
//                  pack(lo(2p),lo(2p+1)), pack(lo(2p+8),lo(2p+9))}, p = ks*8+tq
__global__ void prep_kernel(const float* __restrict__ wih,
                            const float* __restrict__ whh) {
    int e = blockIdx.x * blockDim.x + threadIdx.x;   // 0..49151
    if (e == 0) g_maxd = 0;
    if (e >= G3*64) return;
    int n  = e >> 6;
    int r  = e & 63;
    int ks = r >> 2, tq = r & 3;
    int p  = ks*8 + tq;
    int k0 = 2*p;
    #pragma unroll
    for (int w = 0; w < 2; w++) {
        const float* src = w ? whh : wih;
        float f0 = src[n*256 + k0],     f1 = src[n*256 + k0 + 1];
        float f2 = src[n*256 + k0 + 8], f3 = src[n*256 + k0 + 9];
        __nv_bfloat16 h0 = __float2bfloat16(f0), h1 = __float2bfloat16(f1);
        __nv_bfloat16 h2 = __float2bfloat16(f2), h3 = __float2bfloat16(f3);
        uint4 v;
        v.x = pack_b2(__bfloat162float(h0), __bfloat162float(h1));
        v.y = pack_b2(__bfloat162float(h2), __bfloat162float(h3));
        v.z = pack_b2(f0 - __bfloat162float(h0), f1 - __bfloat162float(h1));
        v.w = pack_b2(f2 - __bfloat162float(h2), f3 - __bfloat162float(h3));
        (w ? g_whh_p : g_wih_p)[e] = v;
    }
}

// ---------------- embeddings + first half of output ----------------------------
__global__ void embed_kernel(const int* __restrict__ node_types,
                             const int* __restrict__ node_vals,
                             const int* __restrict__ child_positions,
                             const float* __restrict__ type_emb,
                             const float* __restrict__ pos_table,
                             const float* __restrict__ token_emb,
                             float* __restrict__ out) {
    int id  = blockIdx.x;
    int tid = threadIdx.x;
    int b = id >> 10, n = id & 1023;
    int tt = node_types[id];
    int cp = child_positions[id];
    int v0 = node_vals[2*id];
    int v1 = node_vals[2*id + 1];
    float x = type_emb[tt*DD + tid] * 4.0f + pos_table[cp*DD + tid] * 0.25f;
    float tok = token_emb[v0*DD + tid] + token_emb[v1*DD + tid];
    __nv_bfloat16 hi = __float2bfloat16(x);
    __nv_bfloat16 lo = __float2bfloat16(x - __bfloat162float(hi));
    g_x_hi[id*DD + tid] = hi;
    g_x_lo[id*DD + tid] = lo;
    out[((n*BB + b) * (DD+HH)) + tid] = x + tok * 2.0f;
}

// ---------------- GI GEMM via mma.sync (M64 per CTA, 3 N-chunks of 256) --------
#define GI_SMEM (2 * 64 * PITCH * 2)   // hi+lo A tiles, bytes

__global__ void __launch_bounds__(256, 1) gi_mma_kernel(const float* __restrict__ bih) {
    extern __shared__ __nv_bfloat16 sA[];       // [2][64][PITCH]
    __nv_bfloat16* sHi = sA;
    __nv_bfloat16* sLo = sA + 64 * PITCH;
    int tid = threadIdx.x;
    int wid = tid >> 5, lane = tid & 31;
    int gid = lane >> 2, tq = lane & 3;
    int wm = wid >> 2, wc = wid & 3;
    long row0 = (long)blockIdx.x * 64;

    // fill A: 64 rows x 128 u32 per precision
    {
        const uint32_t* srcH = (const uint32_t*)g_x_hi + row0 * 128;
        const uint32_t* srcL = (const uint32_t*)g_x_lo + row0 * 128;
        uint32_t* dH = (uint32_t*)sHi;
        uint32_t* dL = (uint32_t*)sLo;
        for (int idx = tid; idx < 64 * 128; idx += 256) {
            int m = idx >> 7, j = idx & 127;
            dH[m * (PITCH/2) + j] = srcH[idx];
            dL[m * (PITCH/2) + j] = srcL[idx];
        }
    }
    __syncthreads();

    // per-lane ldmatrix address offset (bytes within a 16-row tile)
    int l7 = lane & 7, q = lane >> 3;
    uint32_t aoff = (((q & 1) * 8 + l7) * (PITCH/2) + (q >> 1) * 4) * 4;
    uint32_t sHiA = smem_u32(sHi), sLoA = smem_u32(sLo);
    uint32_t adH[2], adL[2];
    #pragma unroll
    for (int mt = 0; mt < 2; mt++) {
        int m0 = wm * 32 + mt * 16;
        adH[mt] = sHiA + m0 * (PITCH*2) + aoff;
        adL[mt] = sLoA + m0 * (PITCH*2) + aoff;
    }

    for (int c = 0; c < 3; c++) {
        float C[2][8][4];
        #pragma unroll
        for (int mt = 0; mt < 2; mt++)
            #pragma unroll
            for (int nt = 0; nt < 8; nt++)
                #pragma unroll
                for (int qq = 0; qq < 4; qq++) C[mt][nt][qq] = 0.0f;

        #pragma unroll 2
        for (int ks = 0; ks < 16; ks++) {
            uint32_t aH[2][4], aL[2][4];
            #pragma unroll
            for (int mt = 0; mt < 2; mt++) {
                ldsm4(adH[mt] + ks * 32, aH[mt]);
                ldsm4(adL[mt] + ks * 32, aL[mt]);
            }
            #pragma unroll
            for (int nt = 0; nt < 8; nt++) {
                int n = c * 256 + wc * 64 + nt * 8 + gid;
                uint4 bw = g_wih_p[n * 64 + ks * 4 + tq];
                #pragma unroll
                for (int mt = 0; mt < 2; mt++) {
                    mma16816(C[mt][nt], aH[mt][0], aH[mt][1], aH[mt][2], aH[mt][3], bw.x, bw.y);
                    mma16816(C[mt][nt], aL[mt][0], aL[mt][1], aL[mt][2], aL[mt][3], bw.x, bw.y);
                    mma16816(C[mt][nt], aH[mt][0], aH[mt][1], aH[mt][2], aH[mt][3], bw.z, bw.w);
                }
            }
        }
        // epilogue: add bias, store fp32
        #pragma unroll
        for (int mt = 0; mt < 2; mt++) {
            long r = row0 + wm * 32 + mt * 16 + gid;
            #pragma unroll
            for (int nt = 0; nt < 8; nt++) {
                int col = c * 256 + wc * 64 + nt * 8 + tq * 2;
                float2 bv = *(const float2*)(bih + col);
                float2 v0 = make_float2(C[mt][nt][0] + bv.x, C[mt][nt][1] + bv.y);
                float2 v1 = make_float2(C[mt][nt][2] + bv.x, C[mt][nt][3] + bv.y);
                *(float2*)(g_gi + r * G3 + col)       = v0;
                *(float2*)(g_gi + (r + 8) * G3 + col) = v1;
            }
        }
    }
}

// ---------------- scheduler S1: depths + per-b level counts --------------------
__global__ void sched1_kernel(const int* __restrict__ lpi) {
    __shared__ int            slpi[NN];
    __shared__ unsigned short sdep[NN];
    __shared__ int            scnt[NN];
    int b = blockIdx.x, tid = threadIdx.x;
    for (int i = tid; i < NN; i += blockDim.x) { slpi[i] = lpi[b*NN + i]; scnt[i] = 0; }
    __syncthreads();
    if (tid == 0) {
        int maxd = 0;
        sdep[0] = 0; scnt[0] = 1;
        for (int i = 1; i < NN; i++) {
            int d = sdep[slpi[i]] + 1;
            sdep[i] = (unsigned short)d;
            scnt[d]++;
            if (d > maxd) maxd = d;
        }
        atomicMax(&g_maxd, maxd);
    }
    __syncthreads();
    for (int i = tid; i < NN; i += blockDim.x) {
        g_depth[b*NN + i] = sdep[i];
        g_cnt  [b*NN + i] = scnt[i];
    }
}

// ---------------- scheduler S2 -------------------------------------------------
__global__ void __launch_bounds__(1024) sched2_kernel() {
    __shared__ int stot[NN];
    __shared__ int srptr[NN+1];
    int r = threadIdx.x;
    int s = 0;
    for (int b = 0; b < BB; b++) {
        g_rbstart[b*NN + r] = s;
        s += g_cnt[b*NN + r];
    }
    stot[r] = s;
    __syncthreads();
    if (r == 0) {
        int acc = 0;
        for (int i = 0; i < NN; i++) { srptr[i] = acc; acc += stot[i]; }
        srptr[NN] = acc;
    }
    __syncthreads();
    for (int b = 0; b < BB; b++) g_rbstart[b*NN + r] += srptr[r];
    g_rptr[r] = srptr[r];
    if (r == 0) g_rptr[NN] = srptr[NN];
}

// ---------------- scheduler S3 -------------------------------------------------
__global__ void sched3_kernel() {
    __shared__ int            scur[NN];
    __shared__ unsigned short sdep[NN];
    int b = blockIdx.x, tid = threadIdx.x;
    for (int i = tid; i < NN; i += blockDim.x) {
        scur[i] = g_rbstart[b*NN + i];
        sdep[i] = g_depth  [b*NN + i];
    }
    __syncthreads();
    if (tid == 0) {
        for (int i = 0; i < NN; i++) {
            int r = sdep[i];
            g_sched[scur[r]++] = (b << 10) | i;
        }
    }
}

// ---------------- persistent level-parallel GRU (mma.sync) ---------------------
__device__ __forceinline__ void grid_barrier() {
    __threadfence();
    __syncthreads();
    if (threadIdx.x == 0) {
        unsigned gen = *(volatile unsigned*)&g_bar_gen;
        if (atomicAdd(&g_bar_count, 1u) == (unsigned)gridDim.x - 1u) {
            g_bar_count = 0u;
            __threadfence();
            *(volatile unsigned*)&g_bar_gen = gen + 1u;
        } else {
            while (*(volatile unsigned*)&g_bar_gen == gen) { }
        }
        __threadfence();
    }
    __syncthreads();
}

// warp wid owns n-tiles {wid + 8*jj : jj=0..11}; triplet (c, c+256, c+512)
// for c in warp's base cols lives in jj, jj+4, jj+8 of the SAME warp.
__global__ void __launch_bounds__(256, 1) seq_kernel(const int* __restrict__ lpi,
                                                     const float* __restrict__ bhh,
                                                     float* __restrict__ out) {
    __shared__ __nv_bfloat16 sHi[TG * PITCH];
    __shared__ __nv_bfloat16 sLo[TG * PITCH];
    __shared__ int sMeta[TG];
    __shared__ int sPar[TG];
    int tid = threadIdx.x;
    int wid = tid >> 5, lane = tid & 31;
    int gid = lane >> 2, tq = lane & 3;
    int maxd = g_maxd;

    uint32_t* dH = (uint32_t*)sHi;
    uint32_t* dL = (uint32_t*)sLo;

    int l7 = lane & 7, q = lane >> 3;
    uint32_t aoff = (((q & 1) * 8 + l7) * (PITCH/2) + (q >> 1) * 4) * 4;
    uint32_t sHiA = smem_u32(sHi), sLoA = smem_u32(sLo);
    uint32_t adH[2], adL[2];
    #pragma unroll
    for (int mt = 0; mt < 2; mt++) {
        adH[mt] = sHiA + (mt * 16) * (PITCH*2) + aoff;
        adL[mt] = sLoA + (mt * 16) * (PITCH*2) + aoff;
    }

    for (int r = 0; r <= maxd; r++) {
        int start = g_rptr[r];
        int cnt   = g_rptr[r+1] - start;
        int ngroups = (cnt + TG - 1) / TG;
        for (int g = blockIdx.x; g < ngroups; g += gridDim.x) {
            int t0 = start + g * TG;
            int tc = cnt - g * TG; if (tc > TG) tc = TG;
            if (tid < TG) {
                if (tid < tc) {
                    int s = g_sched[t0 + tid];
                    sMeta[tid] = s;
                    int b = s >> 10, i = s & 1023;
                    sPar[tid] = (i == 0) ? -1 : ((b << 10) | lpi[b*NN + i]);
                } else { sMeta[tid] = 0; sPar[tid] = -1; }
            }
            __syncthreads();
            // gather parents -> split bf16 smem
            for (int idx = tid; idx < TG * 64; idx += 256) {
                int t = idx >> 6, k4 = idx & 63;
                int pr = sPar[t];
                float4 v;
                if (pr < 0) { v.x=v.y=v.z=v.w=0.f; }
                else        { v = ((const float4*)&g_h[(long)pr*HH])[k4]; }
                float hx = __bfloat162float(__float2bfloat16(v.x));
                float hy = __bfloat162float(__float2bfloat16(v.y));
                float hz = __bfloat162float(__float2bfloat16(v.z));
                float hw = __bfloat162float(__float2bfloat16(v.w));
                int o = t * (PITCH/2) + k4 * 2;
                dH[o]   = pack_b2(hx, hy);
                dH[o+1] = pack_b2(hz, hw);
                dL[o]   = pack_b2(v.x - hx, v.y - hy);
                dL[o+1] = pack_b2(v.z - hz, v.w - hw);
            }
            __syncthreads();

            float C[2][12][4];
            #pragma unroll
            for (int mt = 0; mt < 2; mt++)
                #pragma unroll
                for (int jj = 0; jj < 12; jj++)
                    #pragma unroll
                    for (int qq = 0; qq < 4; qq++) C[mt][jj][qq] = 0.0f;

            #pragma unroll 1
            for (int ks = 0; ks < 16; ks++) {
                uint32_t aH[2][4], aL[2][4];
                #pragma unroll
                for (int mt = 0; mt < 2; mt++) {
                    ldsm4(adH[mt] + ks * 32, aH[mt]);
                    ldsm4(adL[mt] + ks * 32, aL[mt]);
                }
                #pragma unroll
                for (int jj = 0; jj < 12; jj++) {
                    int n = 8 * wid + 64 * jj + gid;
                    uint4 bw = g_whh_p[n * 64 + ks * 4 + tq];
                    #pragma unroll
                    for (int mt = 0; mt < 2; mt++) {
                        mma16816(C[mt][jj], aH[mt][0], aH[mt][1], aH[mt][2], aH[mt][3], bw.x, bw.y);
                        mma16816(C[mt][jj], aL[mt][0], aL[mt][1], aL[mt][2], aL[mt][3], bw.x, bw.y);
                        mma16816(C[mt][jj], aH[mt][0], aH[mt][1], aH[mt][2], aH[mt][3], bw.z, bw.w);
                    }
                }
            }

            // fused GRU epilogue: warp holds (r,z,n) triplets for its cols
            #pragma unroll
            for (int jj = 0; jj < 4; jj++) {
                int cp = 8 * (wid + 8 * jj) + tq * 2;     // base col in [0,256)
                float2 br = *(const float2*)(bhh + cp);
                float2 bz = *(const float2*)(bhh + 256 + cp);
                float2 bn = *(const float2*)(bhh + 512 + cp);
                #pragma unroll
                for (int mt = 0; mt < 2; mt++) {
                    #pragma unroll
                    for (int rh = 0; rh < 2; rh++) {
                        int lr = mt * 16 + gid + rh * 8;
                        if (lr >= tc) continue;
                        float cr0 = C[mt][jj][rh*2],   cr1 = C[mt][jj][rh*2+1];
                        float cz0 = C[mt][jj+4][rh*2], cz1 = C[mt][jj+4][rh*2+1];
                        float cn0 = C[mt][jj+8][rh*2], cn1 = C[mt][jj+8][rh*2+1];
                        int s = sMeta[lr];
                        long row = (long)s;
                        int b = s >> 10, i = s & 1023;
                        const float* gp = g_gi + row * G3;
                        float2 gr = *(const float2*)(gp + cp);
                        float2 gz = *(const float2*)(gp + 256 + cp);
                        float2 gn = *(const float2*)(gp + 512 + cp);
                        int ho = lr * (PITCH/2) + cp / 2;
                        float2 fh = unpack_b2(((const uint32_t*)sHi)[ho]);
                        float2 fl = unpack_b2(((const uint32_t*)sLo)[ho]);
                        float hp0 = fh.x + fl.x, hp1 = fh.y + fl.y;
                        float rg0 = sigm(gr.x + cr0 + br.x);
                        float rg1 = sigm(gr.y + cr1 + br.y);
                        float zg0 = sigm(gz.x + cz0 + bz.x);
                        float zg1 = sigm(gz.y + cz1 + bz.y);
                        float ng0 = tanhf(gn.x + (cn0 + bn.x) * rg0);
                        float ng1 = tanhf(gn.y + (cn1 + bn.y) * rg1);
                        float h0 = (1.0f - zg0) * ng0 + zg0 * hp0;
                        float h1 = (1.0f - zg1) * ng1 + zg1 * hp1;
                        *(float2*)(g_h + row * HH + cp) = make_float2(h0, h1);
                        *(float2*)(out + ((long)(i*BB + b) * (DD+HH)) + DD + cp) = make_float2(h0, h1);
                    }
                }
            }
            __syncthreads();
        }
        grid_barrier();
    }
}

// ---------------- launch -------------------------------------------------------
extern "C" void kernel_launch(void* const* d_in, const int* in_sizes, int n_in,
                              void* d_out, int out_size) {
    const int*   node_types      = (const int*)  d_in[0];
    const int*   node_vals       = (const int*)  d_in[1];
    const int*   last_parent     = (const int*)  d_in[3];
    const int*   child_positions = (const int*)  d_in[4];
    const float* type_emb        = (const float*)d_in[5];
    const float* pos_table       = (const float*)d_in[6];
    const float* token_emb       = (const float*)d_in[7];
    const float* w_ih            = (const float*)d_in[8];
    const float* w_hh            = (const float*)d_in[9];
    const float* b_ih            = (const float*)d_in[10];
    const float* b_hh            = (const float*)d_in[11];
    float* out = (float*)d_out;

    cudaFuncSetAttribute(gi_mma_kernel, cudaFuncAttributeMaxDynamicSharedMemorySize, GI_SMEM);

    prep_kernel<<<192, 256>>>(w_ih, w_hh);
    embed_kernel<<<NB, 256>>>(node_types, node_vals, child_positions,
                              type_emb, pos_table, token_emb, out);
    gi_mma_kernel<<<NB/64, 256, GI_SMEM>>>(b_ih);
    sched1_kernel<<<BB, 256>>>(last_parent);
    sched2_kernel<<<1, 1024>>>();
    sched3_kernel<<<BB, 256>>>();
    seq_kernel<<<SEQ_CTAS, 256>>>(last_parent, b_hh, out);
}

// round 5
// speedup vs baseline: 3.5792x; 1.1749x over previous
#include <cuda_runtime.h>
#include <cuda_fp16.h>
#include <math.h>
#include <stdint.h>

// Problem constants
#define BB   64
#define NN   1024
#define DD   256
#define HH   256
#define G3   768            // 3*H
#define NB   (BB*NN)        // 65536 rows
#define TG   32             // rows per group in seq kernel
#define SEQ_CTAS 148
#define PITCH 264           // fp16 pitch for A smem tiles (132 u32; LDSM conflict-free)

// ---------------- scratch (device globals) ------------------------------------
__device__ float g_gi  [NB*G3];                 // input gates (192 MB)
__device__ float g_h   [NB*HH];                 // hidden states (64 MB)
__device__ __half g_x_h[NB*DD];                 // fp16 activations
// frag-packed weights (fp16 split): [n][ks][tq] -> uint4 {hi0, hi1, lo0, lo1}
__device__ __align__(16) uint4 g_wih_p[G3*64];
__device__ __align__(16) uint4 g_whh_p[G3*64];
__device__ unsigned short g_depth[NB];
__device__ int   g_cnt    [BB*NN];
__device__ int   g_rbstart[BB*NN];
__device__ int   g_rptr   [NN+1];
__device__ int   g_sched  [NB];
__device__ int   g_maxd;
__device__ unsigned g_bar_count = 0;
__device__ unsigned g_bar_gen   = 0;

// ---------------- helpers ------------------------------------------------------
__device__ __forceinline__ void mma16816(float* c,
        uint32_t a0, uint32_t a1, uint32_t a2, uint32_t a3,
        uint32_t b0, uint32_t b1) {
    asm volatile("mma.sync.aligned.m16n8k16.row.col.f32.f16.f16.f32 "
        "{%0,%1,%2,%3}, {%4,%5,%6,%7}, {%8,%9}, {%0,%1,%2,%3};"
        : "+f"(c[0]), "+f"(c[1]), "+f"(c[2]), "+f"(c[3])
        : "r"(a0), "r"(a1), "r"(a2), "r"(a3), "r"(b0), "r"(b1));
}
__device__ __forceinline__ void ldsm4(uint32_t addr, uint32_t* r) {
    asm volatile("ldmatrix.sync.aligned.m8n8.x4.shared.b16 {%0,%1,%2,%3}, [%4];"
        : "=r"(r[0]), "=r"(r[1]), "=r"(r[2]), "=r"(r[3]) : "r"(addr));
}
__device__ __forceinline__ uint32_t smem_u32(const void* p) {
    uint32_t a;
    asm("{ .reg .u64 t; cvta.to.shared.u64 t, %1; cvt.u32.u64 %0, t; }" : "=r"(a) : "l"(p));
    return a;
}
__device__ __forceinline__ float2 unpack_h2(uint32_t v) {
    __half2 h = *reinterpret_cast<__half2*>(&v);
    return __half22float2(h);
}
__device__ __forceinline__ uint32_t pack_h2(float x, float y) {
    __half2 h = __floats2half2_rn(x, y);
    return *reinterpret_cast<uint32_t*>(&h);
}
__device__ __forceinline__ float sigm(float x) { return 1.0f / (1.0f + expf(-x)); }

// ---------------- prep: frag-pack both weight matrices (fp16 split) ------------
// pw[n][ks][tq] = {pack(hi(2p),hi(2p+1)), pack(hi(2p+8),hi(2p+9)),
//                  pack(lo(2p),lo(2p+1)), pack(lo(2p+8),lo(2p+9))}, p = ks*8+tq
__global__ void prep_kernel(const float* __restrict__ wih,
                            const float* __restrict__ whh) {
    int e = blockIdx.x * blockDim.x + threadIdx.x;   // 0..49151
    if (e == 0) g_maxd = 0;
    if (e >= G3*64) return;
    int n  = e >> 6;
    int r  = e & 63;
    int ks = r >> 2, tq = r & 3;
    int p  = ks*8 + tq;
    int k0 = 2*p;
    #pragma unroll
    for (int w = 0; w < 2; w++) {
        const float* src = w ? whh : wih;
        float f0 = src[n*256 + k0],     f1 = src[n*256 + k0 + 1];
        float f2 = src[n*256 + k0 + 8], f3 = src[n*256 + k0 + 9];
        __half h0 = __float2half(f0), h1 = __float2half(f1);
        __half h2 = __float2half(f2), h3 = __float2half(f3);
        uint4 v;
        v.x = pack_h2(__half2float(h0), __half2float(h1));
        v.y = pack_h2(__half2float(h2), __half2float(h3));
        v.z = pack_h2(f0 - __half2float(h0), f1 - __half2float(h1));
        v.w = pack_h2(f2 - __half2float(h2), f3 - __half2float(h3));
        (w ? g_whh_p : g_wih_p)[e] = v;
    }
}

// ---------------- embeddings + first half of output ----------------------------
__global__ void embed_kernel(const int* __restrict__ node_types,
                             const int* __restrict__ node_vals,
                             const int* __restrict__ child_positions,
                             const float* __restrict__ type_emb,
                             const float* __restrict__ pos_table,
                             const float* __restrict__ token_emb,
                             float* __restrict__ out) {
    int id  = blockIdx.x;
    int tid = threadIdx.x;
    int b = id >> 10, n = id & 1023;
    int tt = node_types[id];
    int cp = child_positions[id];
    int v0 = node_vals[2*id];
    int v1 = node_vals[2*id + 1];
    float x = type_emb[tt*DD + tid] * 4.0f + pos_table[cp*DD + tid] * 0.25f;
    float tok = token_emb[v0*DD + tid] + token_emb[v1*DD + tid];
    g_x_h[id*DD + tid] = __float2half(x);
    out[((n*BB + b) * (DD+HH)) + tid] = x + tok * 2.0f;
}

// ---------------- GI GEMM via mma.sync (M64 per CTA, 3 N-chunks of 256) --------
#define GI_SMEM (64 * PITCH * 2)   // fp16 A tile, bytes

__global__ void __launch_bounds__(256, 1) gi_mma_kernel(const float* __restrict__ bih) {
    extern __shared__ __half sA[];              // [64][PITCH]
    int tid = threadIdx.x;
    int wid = tid >> 5, lane = tid & 31;
    int gid = lane >> 2, tq = lane & 3;
    int wm = wid >> 2, wc = wid & 3;
    long row0 = (long)blockIdx.x * 64;

    // fill A: 64 rows x 128 u32
    {
        const uint32_t* src = (const uint32_t*)g_x_h + row0 * 128;
        uint32_t* dst = (uint32_t*)sA;
        for (int idx = tid; idx < 64 * 128; idx += 256) {
            int m = idx >> 7, j = idx & 127;
            dst[m * (PITCH/2) + j] = src[idx];
        }
    }
    __syncthreads();

    // per-lane ldmatrix address offset (bytes within a 16-row tile)
    int l7 = lane & 7, q = lane >> 3;
    uint32_t aoff = (((q & 1) * 8 + l7) * (PITCH/2) + (q >> 1) * 4) * 4;
    uint32_t sAA = smem_u32(sA);
    uint32_t ad[2];
    #pragma unroll
    for (int mt = 0; mt < 2; mt++)
        ad[mt] = sAA + (wm * 32 + mt * 16) * (PITCH*2) + aoff;

    for (int c = 0; c < 3; c++) {
        float C[2][8][4];
        #pragma unroll
        for (int mt = 0; mt < 2; mt++)
            #pragma unroll
            for (int nt = 0; nt < 8; nt++)
                #pragma unroll
                for (int qq = 0; qq < 4; qq++) C[mt][nt][qq] = 0.0f;

        #pragma unroll 2
        for (int ks = 0; ks < 16; ks++) {
            uint32_t aF[2][4];
            #pragma unroll
            for (int mt = 0; mt < 2; mt++) ldsm4(ad[mt] + ks * 32, aF[mt]);
            #pragma unroll
            for (int nt = 0; nt < 8; nt++) {
                int n = c * 256 + wc * 64 + nt * 8 + gid;
                uint4 bw = g_wih_p[n * 64 + ks * 4 + tq];
                #pragma unroll
                for (int mt = 0; mt < 2; mt++) {
                    mma16816(C[mt][nt], aF[mt][0], aF[mt][1], aF[mt][2], aF[mt][3], bw.x, bw.y);
                    mma16816(C[mt][nt], aF[mt][0], aF[mt][1], aF[mt][2], aF[mt][3], bw.z, bw.w);
                }
            }
        }
        // epilogue: add bias, store fp32
        #pragma unroll
        for (int mt = 0; mt < 2; mt++) {
            long r = row0 + wm * 32 + mt * 16 + gid;
            #pragma unroll
            for (int nt = 0; nt < 8; nt++) {
                int col = c * 256 + wc * 64 + nt * 8 + tq * 2;
                float2 bv = *(const float2*)(bih + col);
                float2 v0 = make_float2(C[mt][nt][0] + bv.x, C[mt][nt][1] + bv.y);
                float2 v1 = make_float2(C[mt][nt][2] + bv.x, C[mt][nt][3] + bv.y);
                *(float2*)(g_gi + r * G3 + col)       = v0;
                *(float2*)(g_gi + (r + 8) * G3 + col) = v1;
            }
        }
    }
}

// ---------------- scheduler S1: parallel pointer-doubling depths ---------------
__global__ void __launch_bounds__(256) sched1_kernel(const int* __restrict__ lpi) {
    __shared__ int            jb[NN];
    __shared__ unsigned short db[NN];
    __shared__ int            scnt[NN];
    __shared__ int            smax;
    int b = blockIdx.x, tid = threadIdx.x;
    if (tid == 0) smax = 0;
    for (int i = tid; i < NN; i += 256) {
        jb[i] = (i == 0) ? 0 : lpi[b*NN + i];
        db[i] = (i == 0) ? 0 : 1;
        scnt[i] = 0;
    }
    __syncthreads();
    #pragma unroll 1
    for (int s = 0; s < 10; s++) {
        int nd[4], nj[4];
        #pragma unroll
        for (int u = 0; u < 4; u++) {
            int i = tid + u * 256;
            int j = jb[i];
            nd[u] = db[i] + db[j];
            nj[u] = jb[j];
        }
        __syncthreads();
        #pragma unroll
        for (int u = 0; u < 4; u++) {
            int i = tid + u * 256;
            db[i] = (unsigned short)nd[u];
            jb[i] = nj[u];
        }
        __syncthreads();
    }
    int lm = 0;
    for (int i = tid; i < NN; i += 256) {
        atomicAdd(&scnt[db[i]], 1);
        lm = max(lm, (int)db[i]);
    }
    atomicMax(&smax, lm);
    __syncthreads();
    if (tid == 0) atomicMax(&g_maxd, smax);
    for (int i = tid; i < NN; i += 256) {
        g_depth[b*NN + i] = db[i];
        g_cnt  [b*NN + i] = scnt[i];
    }
}

// ---------------- scheduler S2 -------------------------------------------------
__global__ void __launch_bounds__(1024) sched2_kernel() {
    __shared__ int stot[NN];
    __shared__ int srptr[NN+1];
    int r = threadIdx.x;
    int s = 0;
    for (int b = 0; b < BB; b++) {
        g_rbstart[b*NN + r] = s;
        s += g_cnt[b*NN + r];
    }
    stot[r] = s;
    __syncthreads();
    if (r == 0) {
        int acc = 0;
        for (int i = 0; i < NN; i++) { srptr[i] = acc; acc += stot[i]; }
        srptr[NN] = acc;
    }
    __syncthreads();
    for (int b = 0; b < BB; b++) g_rbstart[b*NN + r] += srptr[r];
    g_rptr[r] = srptr[r];
    if (r == 0) g_rptr[NN] = srptr[NN];
}

// ---------------- scheduler S3: parallel scatter (level order irrelevant) ------
__global__ void __launch_bounds__(256) sched3_kernel() {
    __shared__ int scur[NN];
    int b = blockIdx.x, tid = threadIdx.x;
    for (int i = tid; i < NN; i += 256) scur[i] = g_rbstart[b*NN + i];
    __syncthreads();
    for (int i = tid; i < NN; i += 256) {
        int d = g_depth[b*NN + i];
        int pos = atomicAdd(&scur[d], 1);
        g_sched[pos] = (b << 10) | i;
    }
}

// ---------------- persistent level-parallel GRU (mma.sync) ---------------------
__device__ __forceinline__ void grid_barrier() {
    __threadfence();
    __syncthreads();
    if (threadIdx.x == 0) {
        unsigned gen = *(volatile unsigned*)&g_bar_gen;
        if (atomicAdd(&g_bar_count, 1u) == (unsigned)gridDim.x - 1u) {
            g_bar_count = 0u;
            __threadfence();
            *(volatile unsigned*)&g_bar_gen = gen + 1u;
        } else {
            while (*(volatile unsigned*)&g_bar_gen == gen) { }
        }
        __threadfence();
    }
    __syncthreads();
}

// warp wid owns n-tiles {wid + 8*jj : jj=0..11}; triplet (c, c+256, c+512)
// for c in warp's base cols lives in jj, jj+4, jj+8 of the SAME warp.
__global__ void __launch_bounds__(256, 1) seq_kernel(const int* __restrict__ lpi,
                                                     const float* __restrict__ bhh,
                                                     float* __restrict__ out) {
    __shared__ __half sH[TG * PITCH];
    __shared__ int sMeta[TG];
    __shared__ int sPar[TG];
    int tid = threadIdx.x;
    int wid = tid >> 5, lane = tid & 31;
    int gid = lane >> 2, tq = lane & 3;
    int maxd = g_maxd;

    uint32_t* dH = (uint32_t*)sH;

    int l7 = lane & 7, q = lane >> 3;
    uint32_t aoff = (((q & 1) * 8 + l7) * (PITCH/2) + (q >> 1) * 4) * 4;
    uint32_t sHA = smem_u32(sH);
    uint32_t ad[2];
    #pragma unroll
    for (int mt = 0; mt < 2; mt++)
        ad[mt] = sHA + (mt * 16) * (PITCH*2) + aoff;

    for (int r = 0; r <= maxd; r++) {
        int start = g_rptr[r];
        int cnt   = g_rptr[r+1] - start;
        int ngroups = (cnt + TG - 1) / TG;
        for (int g = blockIdx.x; g < ngroups; g += gridDim.x) {
            int t0 = start + g * TG;
            int tc = cnt - g * TG; if (tc > TG) tc = TG;
            if (tid < TG) {
                if (tid < tc) {
                    int s = g_sched[t0 + tid];
                    sMeta[tid] = s;
                    int b = s >> 10, i = s & 1023;
                    sPar[tid] = (i == 0) ? -1 : ((b << 10) | lpi[b*NN + i]);
                } else { sMeta[tid] = 0; sPar[tid] = -1; }
            }
            __syncthreads();
            // gather parents -> fp16 smem
            for (int idx = tid; idx < TG * 64; idx += 256) {
                int t = idx >> 6, k4 = idx & 63;
                int pr = sPar[t];
                float4 v;
                if (pr < 0) { v.x=v.y=v.z=v.w=0.f; }
                else        { v = ((const float4*)&g_h[(long)pr*HH])[k4]; }
                int o = t * (PITCH/2) + k4 * 2;
                dH[o]   = pack_h2(v.x, v.y);
                dH[o+1] = pack_h2(v.z, v.w);
            }
            __syncthreads();

            float C[2][12][4];
            #pragma unroll
            for (int mt = 0; mt < 2; mt++)
                #pragma unroll
                for (int jj = 0; jj < 12; jj++)
                    #pragma unroll
                    for (int qq = 0; qq < 4; qq++) C[mt][jj][qq] = 0.0f;

            #pragma unroll 2
            for (int ks = 0; ks < 16; ks++) {
                uint32_t aF[2][4];
                #pragma unroll
                for (int mt = 0; mt < 2; mt++) ldsm4(ad[mt] + ks * 32, aF[mt]);
                #pragma unroll
                for (int jj = 0; jj < 12; jj++) {
                    int n = 8 * wid + 64 * jj + gid;
                    uint4 bw = g_whh_p[n * 64 + ks * 4 + tq];
                    #pragma unroll
                    for (int mt = 0; mt < 2; mt++) {
                        mma16816(C[mt][jj], aF[mt][0], aF[mt][1], aF[mt][2], aF[mt][3], bw.x, bw.y);
                        mma16816(C[mt][jj], aF[mt][0], aF[mt][1], aF[mt][2], aF[mt][3], bw.z, bw.w);
                    }
                }
            }

            // fused GRU epilogue: warp holds (r,z,n) triplets for its cols
            #pragma unroll
            for (int jj = 0; jj < 4; jj++) {
                int cp = 8 * (wid + 8 * jj) + tq * 2;     // base col in [0,256)
                float2 br = *(const float2*)(bhh + cp);
                float2 bz = *(const float2*)(bhh + 256 + cp);
                float2 bn = *(const float2*)(bhh + 512 + cp);
                #pragma unroll
                for (int mt = 0; mt < 2; mt++) {
                    #pragma unroll
                    for (int rh = 0; rh < 2; rh++) {
                        int lr = mt * 16 + gid + rh * 8;
                        if (lr >= tc) continue;
                        float cr0 = C[mt][jj][rh*2],   cr1 = C[mt][jj][rh*2+1];
                        float cz0 = C[mt][jj+4][rh*2], cz1 = C[mt][jj+4][rh*2+1];
                        float cn0 = C[mt][jj+8][rh*2], cn1 = C[mt][jj+8][rh*2+1];
                        int s = sMeta[lr];
                        long row = (long)s;
                        int b = s >> 10, i = s & 1023;
                        const float* gp = g_gi + row * G3;
                        float2 gr = *(const float2*)(gp + cp);
                        float2 gz = *(const float2*)(gp + 256 + cp);
                        float2 gn = *(const float2*)(gp + 512 + cp);
                        int pr = sPar[lr];
                        float hp0, hp1;
                        if (pr < 0) { hp0 = 0.f; hp1 = 0.f; }
                        else {
                            float2 hv = *(const float2*)(g_h + (long)pr * HH + cp);
                            hp0 = hv.x; hp1 = hv.y;
                        }
                        float rg0 = sigm(gr.x + cr0 + br.x);
                        float rg1 = sigm(gr.y + cr1 + br.y);
                        float zg0 = sigm(gz.x + cz0 + bz.x);
                        float zg1 = sigm(gz.y + cz1 + bz.y);
                        float ng0 = tanhf(gn.x + (cn0 + bn.x) * rg0);
                        float ng1 = tanhf(gn.y + (cn1 + bn.y) * rg1);
                        float h0 = (1.0f - zg0) * ng0 + zg0 * hp0;
                        float h1 = (1.0f - zg1) * ng1 + zg1 * hp1;
                        *(float2*)(g_h + row * HH + cp) = make_float2(h0, h1);
                        *(float2*)(out + ((long)(i*BB + b) * (DD+HH)) + DD + cp) = make_float2(h0, h1);
                    }
                }
            }
            __syncthreads();
        }
        grid_barrier();
    }
}

// ---------------- launch -------------------------------------------------------
extern "C" void kernel_launch(void* const* d_in, const int* in_sizes, int n_in,
                              void* d_out, int out_size) {
    const int*   node_types      = (const int*)  d_in[0];
    const int*   node_vals       = (const int*)  d_in[1];
    const int*   last_parent     = (const int*)  d_in[3];
    const int*   child_positions = (const int*)  d_in[4];
    const float* type_emb        = (const float*)d_in[5];
    const float* pos_table       = (const float*)d_in[6];
    const float* token_emb       = (const float*)d_in[7];
    const float* w_ih            = (const float*)d_in[8];
    const float* w_hh            = (const float*)d_in[9];
    const float* b_ih            = (const float*)d_in[10];
    const float* b_hh            = (const float*)d_in[11];
    float* out = (float*)d_out;

    cudaFuncSetAttribute(gi_mma_kernel, cudaFuncAttributeMaxDynamicSharedMemorySize, GI_SMEM);

    prep_kernel<<<192, 256>>>(w_ih, w_hh);
    embed_kernel<<<NB, 256>>>(node_types, node_vals, child_positions,
                              type_emb, pos_table, token_emb, out);
    gi_mma_kernel<<<NB/64, 256, GI_SMEM>>>(b_ih);
    sched1_kernel<<<BB, 256>>>(last_parent);
    sched2_kernel<<<1, 1024>>>();
    sched3_kernel<<<BB, 256>>>();
    seq_kernel<<<SEQ_CTAS, 256>>>(last_parent, b_hh, out);
}

// round 6
// speedup vs baseline: 4.6515x; 1.2996x over previous
#include <cuda_runtime.h>
#include <cuda_fp16.h>
#include <math.h>
#include <stdint.h>

// Problem constants
#define BB   64
#define NN   1024
#define DD   256
#define HH   256
#define G3   768            // 3*H
#define NB   (BB*NN)        // 65536 rows
#define TG   32             // rows per group in seq kernel
#define SEQ_CTAS 148
#define PITCH 264           // fp16 pitch for A smem tiles (132 u32; LDSM conflict-free)

// ---------------- scratch (device globals) ------------------------------------
__device__ float g_gi  [NB*G3];                 // input gates (192 MB)
__device__ float g_h   [NB*HH];                 // hidden states (64 MB)
__device__ __half g_x_h[NB*DD];                 // fp16 activations
// frag-packed weights (fp16 split): [n][ks][tq] -> uint4 {hi0, hi1, lo0, lo1}
__device__ __align__(16) uint4 g_wih_p[G3*64];
__device__ __align__(16) uint4 g_whh_p[G3*64];
__device__ unsigned short g_depth[NB];
__device__ int   g_cnt    [BB*NN];
__device__ int   g_rbstart[BB*NN];
__device__ int   g_rptr   [NN+1];
__device__ int   g_sched  [NB];
__device__ int   g_maxd;
__device__ unsigned g_bar_count = 0;
__device__ unsigned g_bar_gen   = 0;

// ---------------- helpers ------------------------------------------------------
__device__ __forceinline__ void mma16816(float* c,
        uint32_t a0, uint32_t a1, uint32_t a2, uint32_t a3,
        uint32_t b0, uint32_t b1) {
    asm volatile("mma.sync.aligned.m16n8k16.row.col.f32.f16.f16.f32 "
        "{%0,%1,%2,%3}, {%4,%5,%6,%7}, {%8,%9}, {%0,%1,%2,%3};"
        : "+f"(c[0]), "+f"(c[1]), "+f"(c[2]), "+f"(c[3])
        : "r"(a0), "r"(a1), "r"(a2), "r"(a3), "r"(b0), "r"(b1));
}
__device__ __forceinline__ void ldsm4(uint32_t addr, uint32_t* r) {
    asm volatile("ldmatrix.sync.aligned.m8n8.x4.shared.b16 {%0,%1,%2,%3}, [%4];"
        : "=r"(r[0]), "=r"(r[1]), "=r"(r[2]), "=r"(r[3]) : "r"(addr));
}
__device__ __forceinline__ uint32_t smem_u32(const void* p) {
    uint32_t a;
    asm("{ .reg .u64 t; cvta.to.shared.u64 t, %1; cvt.u32.u64 %0, t; }" : "=r"(a) : "l"(p));
    return a;
}
__device__ __forceinline__ uint32_t pack_h2(float x, float y) {
    __half2 h = __floats2half2_rn(x, y);
    return *reinterpret_cast<uint32_t*>(&h);
}
__device__ __forceinline__ float sigm(float x) { return 1.0f / (1.0f + expf(-x)); }

// ---------------- prep: frag-pack both weight matrices (fp16 split) ------------
__global__ void prep_kernel(const float* __restrict__ wih,
                            const float* __restrict__ whh) {
    int e = blockIdx.x * blockDim.x + threadIdx.x;   // 0..49151
    if (e == 0) g_maxd = 0;
    if (e >= G3*64) return;
    int n  = e >> 6;
    int r  = e & 63;
    int ks = r >> 2, tq = r & 3;
    int p  = ks*8 + tq;
    int k0 = 2*p;
    #pragma unroll
    for (int w = 0; w < 2; w++) {
        const float* src = w ? whh : wih;
        float f0 = src[n*256 + k0],     f1 = src[n*256 + k0 + 1];
        float f2 = src[n*256 + k0 + 8], f3 = src[n*256 + k0 + 9];
        __half h0 = __float2half(f0), h1 = __float2half(f1);
        __half h2 = __float2half(f2), h3 = __float2half(f3);
        uint4 v;
        v.x = pack_h2(__half2float(h0), __half2float(h1));
        v.y = pack_h2(__half2float(h2), __half2float(h3));
        v.z = pack_h2(f0 - __half2float(h0), f1 - __half2float(h1));
        v.w = pack_h2(f2 - __half2float(h2), f3 - __half2float(h3));
        (w ? g_whh_p : g_wih_p)[e] = v;
    }
}

// ---------------- embeddings + first half of output ----------------------------
__global__ void embed_kernel(const int* __restrict__ node_types,
                             const int* __restrict__ node_vals,
                             const int* __restrict__ child_positions,
                             const float* __restrict__ type_emb,
                             const float* __restrict__ pos_table,
                             const float* __restrict__ token_emb,
                             float* __restrict__ out) {
    int id  = blockIdx.x;
    int tid = threadIdx.x;
    int b = id >> 10, n = id & 1023;
    int tt = node_types[id];
    int cp = child_positions[id];
    int v0 = node_vals[2*id];
    int v1 = node_vals[2*id + 1];
    float x = type_emb[tt*DD + tid] * 4.0f + pos_table[cp*DD + tid] * 0.25f;
    float tok = token_emb[v0*DD + tid] + token_emb[v1*DD + tid];
    g_x_h[id*DD + tid] = __float2half(x);
    out[((n*BB + b) * (DD+HH)) + tid] = x + tok * 2.0f;
}

// ---------------- GI GEMM: 512 threads, M=128/CTA, 3 N-chunks of 256 -----------
// warp grid 2x8: wm=wid>>3 (64-row half), wc=wid&7 (32-col slice), mt=0..3
#define GI_SMEM (128 * PITCH * 2)   // fp16 A tile, bytes

__global__ void __launch_bounds__(512, 1) gi_mma_kernel(const float* __restrict__ bih) {
    extern __shared__ __half sA[];              // [128][PITCH]
    int tid = threadIdx.x;
    int wid = tid >> 5, lane = tid & 31;
    int gid = lane >> 2, tq = lane & 3;
    int wm = wid >> 3, wc = wid & 7;
    long row0 = (long)blockIdx.x * 128;

    // fill A: 128 rows x 128 u32
    {
        const uint32_t* src = (const uint32_t*)g_x_h + row0 * 128;
        uint32_t* dst = (uint32_t*)sA;
        for (int idx = tid; idx < 128 * 128; idx += 512) {
            int m = idx >> 7, j = idx & 127;
            dst[m * (PITCH/2) + j] = src[idx];
        }
    }
    __syncthreads();

    int l7 = lane & 7, q = lane >> 3;
    uint32_t aoff = (((q & 1) * 8 + l7) * (PITCH/2) + (q >> 1) * 4) * 4;
    uint32_t sAA = smem_u32(sA);
    uint32_t ad[4];
    #pragma unroll
    for (int mt = 0; mt < 4; mt++)
        ad[mt] = sAA + (wm * 64 + mt * 16) * (PITCH*2) + aoff;

    for (int c = 0; c < 3; c++) {
        float C[4][4][4];
        #pragma unroll
        for (int mt = 0; mt < 4; mt++)
            #pragma unroll
            for (int nt = 0; nt < 4; nt++)
                #pragma unroll
                for (int qq = 0; qq < 4; qq++) C[mt][nt][qq] = 0.0f;

        #pragma unroll 2
        for (int ks = 0; ks < 16; ks++) {
            uint32_t aF[4][4];
            #pragma unroll
            for (int mt = 0; mt < 4; mt++) ldsm4(ad[mt] + ks * 32, aF[mt]);
            #pragma unroll
            for (int nt = 0; nt < 4; nt++) {
                int n = c * 256 + wc * 32 + nt * 8 + gid;
                uint4 bw = g_wih_p[n * 64 + ks * 4 + tq];
                #pragma unroll
                for (int mt = 0; mt < 4; mt++) {
                    mma16816(C[mt][nt], aF[mt][0], aF[mt][1], aF[mt][2], aF[mt][3], bw.x, bw.y);
                    mma16816(C[mt][nt], aF[mt][0], aF[mt][1], aF[mt][2], aF[mt][3], bw.z, bw.w);
                }
            }
        }
        // epilogue: add bias, store fp32
        #pragma unroll
        for (int mt = 0; mt < 4; mt++) {
            long r = row0 + wm * 64 + mt * 16 + gid;
            #pragma unroll
            for (int nt = 0; nt < 4; nt++) {
                int col = c * 256 + wc * 32 + nt * 8 + tq * 2;
                float2 bv = *(const float2*)(bih + col);
                float2 v0 = make_float2(C[mt][nt][0] + bv.x, C[mt][nt][1] + bv.y);
                float2 v1 = make_float2(C[mt][nt][2] + bv.x, C[mt][nt][3] + bv.y);
                *(float2*)(g_gi + r * G3 + col)       = v0;
                *(float2*)(g_gi + (r + 8) * G3 + col) = v1;
            }
        }
    }
}

// ---------------- scheduler S1: parallel pointer-doubling depths ---------------
__global__ void __launch_bounds__(256) sched1_kernel(const int* __restrict__ lpi) {
    __shared__ int            jb[NN];
    __shared__ unsigned short db[NN];
    __shared__ int            scnt[NN];
    __shared__ int            smax;
    int b = blockIdx.x, tid = threadIdx.x;
    if (tid == 0) smax = 0;
    for (int i = tid; i < NN; i += 256) {
        jb[i] = (i == 0) ? 0 : lpi[b*NN + i];
        db[i] = (i == 0) ? 0 : 1;
        scnt[i] = 0;
    }
    __syncthreads();
    #pragma unroll 1
    for (int s = 0; s < 10; s++) {
        int nd[4], nj[4];
        #pragma unroll
        for (int u = 0; u < 4; u++) {
            int i = tid + u * 256;
            int j = jb[i];
            nd[u] = db[i] + db[j];
            nj[u] = jb[j];
        }
        __syncthreads();
        #pragma unroll
        for (int u = 0; u < 4; u++) {
            int i = tid + u * 256;
            db[i] = (unsigned short)nd[u];
            jb[i] = nj[u];
        }
        __syncthreads();
    }
    int lm = 0;
    for (int i = tid; i < NN; i += 256) {
        atomicAdd(&scnt[db[i]], 1);
        lm = max(lm, (int)db[i]);
    }
    atomicMax(&smax, lm);
    __syncthreads();
    if (tid == 0) atomicMax(&g_maxd, smax);
    for (int i = tid; i < NN; i += 256) {
        g_depth[b*NN + i] = db[i];
        g_cnt  [b*NN + i] = scnt[i];
    }
}

// ---------------- scheduler S2 -------------------------------------------------
__global__ void __launch_bounds__(1024) sched2_kernel() {
    __shared__ int stot[NN];
    __shared__ int srptr[NN+1];
    int r = threadIdx.x;
    int s = 0;
    for (int b = 0; b < BB; b++) {
        g_rbstart[b*NN + r] = s;
        s += g_cnt[b*NN + r];
    }
    stot[r] = s;
    __syncthreads();
    if (r == 0) {
        int acc = 0;
        for (int i = 0; i < NN; i++) { srptr[i] = acc; acc += stot[i]; }
        srptr[NN] = acc;
    }
    __syncthreads();
    for (int b = 0; b < BB; b++) g_rbstart[b*NN + r] += srptr[r];
    g_rptr[r] = srptr[r];
    if (r == 0) g_rptr[NN] = srptr[NN];
}

// ---------------- scheduler S3: parallel scatter -------------------------------
__global__ void __launch_bounds__(256) sched3_kernel() {
    __shared__ int scur[NN];
    int b = blockIdx.x, tid = threadIdx.x;
    for (int i = tid; i < NN; i += 256) scur[i] = g_rbstart[b*NN + i];
    __syncthreads();
    for (int i = tid; i < NN; i += 256) {
        int d = g_depth[b*NN + i];
        int pos = atomicAdd(&scur[d], 1);
        g_sched[pos] = (b << 10) | i;
    }
}

// ---------------- persistent level-parallel GRU (mma.sync, 512 thr) ------------
__device__ __forceinline__ void grid_barrier() {
    __threadfence();
    __syncthreads();
    if (threadIdx.x == 0) {
        unsigned gen = *(volatile unsigned*)&g_bar_gen;
        if (atomicAdd(&g_bar_count, 1u) == (unsigned)gridDim.x - 1u) {
            g_bar_count = 0u;
            __threadfence();
            *(volatile unsigned*)&g_bar_gen = gen + 1u;
        } else {
            while (*(volatile unsigned*)&g_bar_gen == gen) { }
        }
        __threadfence();
    }
    __syncthreads();
}

// 16 warps; warp wid owns n-tiles {wid + 16*jj : jj=0..5}; n = 8*wid + 128*jj.
// Gate triplet for base col c = 8*wid + 128*jj (jj=0,1): cols c, c+256, c+512
// live in jj, jj+2, jj+4 of the SAME warp.
__global__ void __launch_bounds__(512, 1) seq_kernel(const int* __restrict__ lpi,
                                                     const float* __restrict__ bhh,
                                                     float* __restrict__ out) {
    __shared__ __half sH[TG * PITCH];
    __shared__ int sMeta[TG];
    __shared__ int sPar[TG];
    int tid = threadIdx.x;
    int wid = tid >> 5, lane = tid & 31;
    int gid = lane >> 2, tq = lane & 3;
    int maxd = g_maxd;

    uint32_t* dH = (uint32_t*)sH;

    int l7 = lane & 7, q = lane >> 3;
    uint32_t aoff = (((q & 1) * 8 + l7) * (PITCH/2) + (q >> 1) * 4) * 4;
    uint32_t sHA = smem_u32(sH);
    uint32_t ad[2];
    #pragma unroll
    for (int mt = 0; mt < 2; mt++)
        ad[mt] = sHA + (mt * 16) * (PITCH*2) + aoff;

    for (int r = 0; r <= maxd; r++) {
        int start = g_rptr[r];
        int cnt   = g_rptr[r+1] - start;
        int ngroups = (cnt + TG - 1) / TG;
        for (int g = blockIdx.x; g < ngroups; g += gridDim.x) {
            int t0 = start + g * TG;
            int tc = cnt - g * TG; if (tc > TG) tc = TG;
            if (tid < TG) {
                if (tid < tc) {
                    int s = g_sched[t0 + tid];
                    sMeta[tid] = s;
                    int b = s >> 10, i = s & 1023;
                    sPar[tid] = (i == 0) ? -1 : ((b << 10) | lpi[b*NN + i]);
                } else { sMeta[tid] = 0; sPar[tid] = -1; }
            }
            __syncthreads();
            // gather parents -> fp16 smem
            for (int idx = tid; idx < TG * 64; idx += 512) {
                int t = idx >> 6, k4 = idx & 63;
                int pr = sPar[t];
                float4 v;
                if (pr < 0) { v.x=v.y=v.z=v.w=0.f; }
                else        { v = ((const float4*)&g_h[(long)pr*HH])[k4]; }
                int o = t * (PITCH/2) + k4 * 2;
                dH[o]   = pack_h2(v.x, v.y);
                dH[o+1] = pack_h2(v.z, v.w);
            }
            __syncthreads();

            float C[2][6][4];
            #pragma unroll
            for (int mt = 0; mt < 2; mt++)
                #pragma unroll
                for (int jj = 0; jj < 6; jj++)
                    #pragma unroll
                    for (int qq = 0; qq < 4; qq++) C[mt][jj][qq] = 0.0f;

            #pragma unroll 2
            for (int ks = 0; ks < 16; ks++) {
                uint32_t aF[2][4];
                #pragma unroll
                for (int mt = 0; mt < 2; mt++) ldsm4(ad[mt] + ks * 32, aF[mt]);
                #pragma unroll
                for (int jj = 0; jj < 6; jj++) {
                    int n = 8 * wid + 128 * jj + gid;
                    uint4 bw = g_whh_p[n * 64 + ks * 4 + tq];
                    #pragma unroll
                    for (int mt = 0; mt < 2; mt++) {
                        mma16816(C[mt][jj], aF[mt][0], aF[mt][1], aF[mt][2], aF[mt][3], bw.x, bw.y);
                        mma16816(C[mt][jj], aF[mt][0], aF[mt][1], aF[mt][2], aF[mt][3], bw.z, bw.w);
                    }
                }
            }

            // fused GRU epilogue
            #pragma unroll
            for (int jj = 0; jj < 2; jj++) {
                int cp = 8 * wid + 128 * jj + tq * 2;     // base col in [0,256)
                float2 br = *(const float2*)(bhh + cp);
                float2 bz = *(const float2*)(bhh + 256 + cp);
                float2 bn = *(const float2*)(bhh + 512 + cp);
                #pragma unroll
                for (int mt = 0; mt < 2; mt++) {
                    #pragma unroll
                    for (int rh = 0; rh < 2; rh++) {
                        int lr = mt * 16 + gid + rh * 8;
                        if (lr >= tc) continue;
                        float cr0 = C[mt][jj][rh*2],   cr1 = C[mt][jj][rh*2+1];
                        float cz0 = C[mt][jj+2][rh*2], cz1 = C[mt][jj+2][rh*2+1];
                        float cn0 = C[mt][jj+4][rh*2], cn1 = C[mt][jj+4][rh*2+1];
                        int s = sMeta[lr];
                        long row = (long)s;
                        int b = s >> 10, i = s & 1023;
                        const float* gp = g_gi + row * G3;
                        float2 gr = *(const float2*)(gp + cp);
                        float2 gz = *(const float2*)(gp + 256 + cp);
                        float2 gn = *(const float2*)(gp + 512 + cp);
                        int pr = sPar[lr];
                        float hp0, hp1;
                        if (pr < 0) { hp0 = 0.f; hp1 = 0.f; }
                        else {
                            float2 hv = *(const float2*)(g_h + (long)pr * HH + cp);
                            hp0 = hv.x; hp1 = hv.y;
                        }
                        float rg0 = sigm(gr.x + cr0 + br.x);
                        float rg1 = sigm(gr.y + cr1 + br.y);
                        float zg0 = sigm(gz.x + cz0 + bz.x);
                        float zg1 = sigm(gz.y + cz1 + bz.y);
                        float ng0 = tanhf(gn.x + (cn0 + bn.x) * rg0);
                        float ng1 = tanhf(gn.y + (cn1 + bn.y) * rg1);
                        float h0 = (1.0f - zg0) * ng0 + zg0 * hp0;
                        float h1 = (1.0f - zg1) * ng1 + zg1 * hp1;
                        *(float2*)(g_h + row * HH + cp) = make_float2(h0, h1);
                        *(float2*)(out + ((long)(i*BB + b) * (DD+HH)) + DD + cp) = make_float2(h0, h1);
                    }
                }
            }
            __syncthreads();
        }
        grid_barrier();
    }
}

// ---------------- launch -------------------------------------------------------
extern "C" void kernel_launch(void* const* d_in, const int* in_sizes, int n_in,
                              void* d_out, int out_size) {
    const int*   node_types      = (const int*)  d_in[0];
    const int*   node_vals       = (const int*)  d_in[1];
    const int*   last_parent     = (const int*)  d_in[3];
    const int*   child_positions = (const int*)  d_in[4];
    const float* type_emb        = (const float*)d_in[5];
    const float* pos_table       = (const float*)d_in[6];
    const float* token_emb       = (const float*)d_in[7];
    const float* w_ih            = (const float*)d_in[8];
    const float* w_hh            = (const float*)d_in[9];
    const float* b_ih            = (const float*)d_in[10];
    const float* b_hh            = (const float*)d_in[11];
    float* out = (float*)d_out;

    cudaFuncSetAttribute(gi_mma_kernel, cudaFuncAttributeMaxDynamicSharedMemorySize, GI_SMEM);

    prep_kernel<<<192, 256>>>(w_ih, w_hh);
    embed_kernel<<<NB, 256>>>(node_types, node_vals, child_positions,
                              type_emb, pos_table, token_emb, out);
    gi_mma_kernel<<<NB/128, 512, GI_SMEM>>>(b_ih);
    sched1_kernel<<<BB, 256>>>(last_parent);
    sched2_kernel<<<1, 1024>>>();
    sched3_kernel<<<BB, 256>>>();
    seq_kernel<<<SEQ_CTAS, 512>>>(last_parent, b_hh, out);
}

// round 7
// speedup vs baseline: 4.7729x; 1.0261x over previous
#include <cuda_runtime.h>
#include <cuda_fp16.h>
#include <math.h>
#include <stdint.h>

// Problem constants
#define BB   64
#define NN   1024
#define DD   256
#define HH   256
#define G3   768            // 3*H
#define NB   (BB*NN)        // 65536 rows
#define TG   32             // rows per group in seq kernel
#define SEQ_CTAS 148
#define PITCH 264           // fp16 pitch for A smem tiles (132 u32; LDSM conflict-free)

// ---------------- scratch (device globals) ------------------------------------
__device__ float g_gi  [NB*G3];                 // input gates (192 MB)
__device__ float g_h   [NB*HH];                 // hidden states (64 MB)
__device__ __half g_x_h[NB*DD];                 // fp16 activations
// gi weights: hi-only frag pack [n][ks][tq] -> uint2 {hi0, hi1}
__device__ __align__(16) uint2 g_wih_h2[G3*64];
// seq weights: fp16 split pack [n][ks][tq] -> uint4 {hi0, hi1, lo0, lo1}
__device__ __align__(16) uint4 g_whh_p[G3*64];
__device__ unsigned short g_depth[NB];
__device__ int   g_cnt    [BB*NN];
__device__ int   g_rbstart[BB*NN];
__device__ int   g_rptr   [NN+1];
__device__ int   g_sched  [NB];
__device__ int   g_maxd;
__device__ unsigned g_bar_count = 0;
__device__ unsigned g_bar_gen   = 0;

// ---------------- helpers ------------------------------------------------------
// NOTE: non-volatile on purpose — pure op, lets ptxas software-pipeline/interleave.
__device__ __forceinline__ void mma16816(float* c,
        uint32_t a0, uint32_t a1, uint32_t a2, uint32_t a3,
        uint32_t b0, uint32_t b1) {
    asm("mma.sync.aligned.m16n8k16.row.col.f32.f16.f16.f32 "
        "{%0,%1,%2,%3}, {%4,%5,%6,%7}, {%8,%9}, {%0,%1,%2,%3};"
        : "+f"(c[0]), "+f"(c[1]), "+f"(c[2]), "+f"(c[3])
        : "r"(a0), "r"(a1), "r"(a2), "r"(a3), "r"(b0), "r"(b1));
}
__device__ __forceinline__ void ldsm4(uint32_t addr, uint32_t* r) {
    asm volatile("ldmatrix.sync.aligned.m8n8.x4.shared.b16 {%0,%1,%2,%3}, [%4];"
        : "=r"(r[0]), "=r"(r[1]), "=r"(r[2]), "=r"(r[3]) : "r"(addr));
}
__device__ __forceinline__ uint32_t smem_u32(const void* p) {
    uint32_t a;
    asm("{ .reg .u64 t; cvta.to.shared.u64 t, %1; cvt.u32.u64 %0, t; }" : "=r"(a) : "l"(p));
    return a;
}
__device__ __forceinline__ uint32_t pack_h2(float x, float y) {
    __half2 h = __floats2half2_rn(x, y);
    return *reinterpret_cast<uint32_t*>(&h);
}
__device__ __forceinline__ float sigm(float x) { return 1.0f / (1.0f + expf(-x)); }

// ---------------- prep: frag-pack weights --------------------------------------
__global__ void prep_kernel(const float* __restrict__ wih,
                            const float* __restrict__ whh) {
    int e = blockIdx.x * blockDim.x + threadIdx.x;   // 0..49151
    if (e == 0) g_maxd = 0;
    if (e >= G3*64) return;
    int n  = e >> 6;
    int r  = e & 63;
    int ks = r >> 2, tq = r & 3;
    int p  = ks*8 + tq;
    int k0 = 2*p;
    // gi weights: hi only
    {
        float f0 = wih[n*256 + k0],     f1 = wih[n*256 + k0 + 1];
        float f2 = wih[n*256 + k0 + 8], f3 = wih[n*256 + k0 + 9];
        uint2 v;
        v.x = pack_h2(f0, f1);
        v.y = pack_h2(f2, f3);
        g_wih_h2[e] = v;
    }
    // seq weights: hi/lo split
    {
        float f0 = whh[n*256 + k0],     f1 = whh[n*256 + k0 + 1];
        float f2 = whh[n*256 + k0 + 8], f3 = whh[n*256 + k0 + 9];
        __half h0 = __float2half(f0), h1 = __float2half(f1);
        __half h2 = __float2half(f2), h3 = __float2half(f3);
        uint4 v;
        v.x = pack_h2(__half2float(h0), __half2float(h1));
        v.y = pack_h2(__half2float(h2), __half2float(h3));
        v.z = pack_h2(f0 - __half2float(h0), f1 - __half2float(h1));
        v.w = pack_h2(f2 - __half2float(h2), f3 - __half2float(h3));
        g_whh_p[e] = v;
    }
}

// ---------------- embeddings + first half of output ----------------------------
__global__ void embed_kernel(const int* __restrict__ node_types,
                             const int* __restrict__ node_vals,
                             const int* __restrict__ child_positions,
                             const float* __restrict__ type_emb,
                             const float* __restrict__ pos_table,
                             const float* __restrict__ token_emb,
                             float* __restrict__ out) {
    int id  = blockIdx.x;
    int tid = threadIdx.x;
    int b = id >> 10, n = id & 1023;
    int tt = node_types[id];
    int cp = child_positions[id];
    int v0 = node_vals[2*id];
    int v1 = node_vals[2*id + 1];
    float x = type_emb[tt*DD + tid] * 4.0f + pos_table[cp*DD + tid] * 0.25f;
    float tok = token_emb[v0*DD + tid] + token_emb[v1*DD + tid];
    g_x_h[id*DD + tid] = __float2half(x);
    out[((n*BB + b) * (DD+HH)) + tid] = x + tok * 2.0f;
}

// ---------------- GI GEMM: 512 threads, M=128/CTA, 3 N-chunks, single fp16 term
#define GI_SMEM (128 * PITCH * 2)   // fp16 A tile, bytes

__global__ void __launch_bounds__(512, 1) gi_mma_kernel(const float* __restrict__ bih) {
    extern __shared__ __half sA[];              // [128][PITCH]
    int tid = threadIdx.x;
    int wid = tid >> 5, lane = tid & 31;
    int gid = lane >> 2, tq = lane & 3;
    int wm = wid >> 3, wc = wid & 7;
    long row0 = (long)blockIdx.x * 128;

    // fill A: 128 rows x 128 u32
    {
        const uint32_t* src = (const uint32_t*)g_x_h + row0 * 128;
        uint32_t* dst = (uint32_t*)sA;
        for (int idx = tid; idx < 128 * 128; idx += 512) {
            int m = idx >> 7, j = idx & 127;
            dst[m * (PITCH/2) + j] = src[idx];
        }
    }
    __syncthreads();

    int l7 = lane & 7, q = lane >> 3;
    uint32_t aoff = (((q & 1) * 8 + l7) * (PITCH/2) + (q >> 1) * 4) * 4;
    uint32_t sAA = smem_u32(sA);
    uint32_t ad[4];
    #pragma unroll
    for (int mt = 0; mt < 4; mt++)
        ad[mt] = sAA + (wm * 64 + mt * 16) * (PITCH*2) + aoff;

    for (int c = 0; c < 3; c++) {
        float C[4][4][4];
        #pragma unroll
        for (int mt = 0; mt < 4; mt++)
            #pragma unroll
            for (int nt = 0; nt < 4; nt++)
                #pragma unroll
                for (int qq = 0; qq < 4; qq++) C[mt][nt][qq] = 0.0f;

        #pragma unroll 2
        for (int ks = 0; ks < 16; ks++) {
            uint32_t aF[4][4];
            #pragma unroll
            for (int mt = 0; mt < 4; mt++) ldsm4(ad[mt] + ks * 32, aF[mt]);
            uint2 bw[4];
            #pragma unroll
            for (int nt = 0; nt < 4; nt++) {
                int n = c * 256 + wc * 32 + nt * 8 + gid;
                bw[nt] = g_wih_h2[n * 64 + ks * 4 + tq];
            }
            #pragma unroll
            for (int nt = 0; nt < 4; nt++)
                #pragma unroll
                for (int mt = 0; mt < 4; mt++)
                    mma16816(C[mt][nt], aF[mt][0], aF[mt][1], aF[mt][2], aF[mt][3],
                             bw[nt].x, bw[nt].y);
        }
        // epilogue: add bias, store fp32
        #pragma unroll
        for (int mt = 0; mt < 4; mt++) {
            long r = row0 + wm * 64 + mt * 16 + gid;
            #pragma unroll
            for (int nt = 0; nt < 4; nt++) {
                int col = c * 256 + wc * 32 + nt * 8 + tq * 2;
                float2 bv = *(const float2*)(bih + col);
                float2 v0 = make_float2(C[mt][nt][0] + bv.x, C[mt][nt][1] + bv.y);
                float2 v1 = make_float2(C[mt][nt][2] + bv.x, C[mt][nt][3] + bv.y);
                *(float2*)(g_gi + r * G3 + col)       = v0;
                *(float2*)(g_gi + (r + 8) * G3 + col) = v1;
            }
        }
    }
}

// ---------------- scheduler S1: parallel pointer-doubling depths ---------------
__global__ void __launch_bounds__(256) sched1_kernel(const int* __restrict__ lpi) {
    __shared__ int            jb[NN];
    __shared__ unsigned short db[NN];
    __shared__ int            scnt[NN];
    __shared__ int            smax;
    int b = blockIdx.x, tid = threadIdx.x;
    if (tid == 0) smax = 0;
    for (int i = tid; i < NN; i += 256) {
        jb[i] = (i == 0) ? 0 : lpi[b*NN + i];
        db[i] = (i == 0) ? 0 : 1;
        scnt[i] = 0;
    }
    __syncthreads();
    #pragma unroll 1
    for (int s = 0; s < 10; s++) {
        int nd[4], nj[4];
        #pragma unroll
        for (int u = 0; u < 4; u++) {
            int i = tid + u * 256;
            int j = jb[i];
            nd[u] = db[i] + db[j];
            nj[u] = jb[j];
        }
        __syncthreads();
        #pragma unroll
        for (int u = 0; u < 4; u++) {
            int i = tid + u * 256;
            db[i] = (unsigned short)nd[u];
            jb[i] = nj[u];
        }
        __syncthreads();
    }
    int lm = 0;
    for (int i = tid; i < NN; i += 256) {
        atomicAdd(&scnt[db[i]], 1);
        lm = max(lm, (int)db[i]);
    }
    atomicMax(&smax, lm);
    __syncthreads();
    if (tid == 0) atomicMax(&g_maxd, smax);
    for (int i = tid; i < NN; i += 256) {
        g_depth[b*NN + i] = db[i];
        g_cnt  [b*NN + i] = scnt[i];
    }
}

// ---------------- scheduler S2 -------------------------------------------------
__global__ void __launch_bounds__(1024) sched2_kernel() {
    __shared__ int stot[NN];
    __shared__ int srptr[NN+1];
    int r = threadIdx.x;
    int s = 0;
    for (int b = 0; b < BB; b++) {
        g_rbstart[b*NN + r] = s;
        s += g_cnt[b*NN + r];
    }
    stot[r] = s;
    __syncthreads();
    if (r == 0) {
        int acc = 0;
        for (int i = 0; i < NN; i++) { srptr[i] = acc; acc += stot[i]; }
        srptr[NN] = acc;
    }
    __syncthreads();
    for (int b = 0; b < BB; b++) g_rbstart[b*NN + r] += srptr[r];
    g_rptr[r] = srptr[r];
    if (r == 0) g_rptr[NN] = srptr[NN];
}

// ---------------- scheduler S3: parallel scatter -------------------------------
__global__ void __launch_bounds__(256) sched3_kernel() {
    __shared__ int scur[NN];
    int b = blockIdx.x, tid = threadIdx.x;
    for (int i = tid; i < NN; i += 256) scur[i] = g_rbstart[b*NN + i];
    __syncthreads();
    for (int i = tid; i < NN; i += 256) {
        int d = g_depth[b*NN + i];
        int pos = atomicAdd(&scur[d], 1);
        g_sched[pos] = (b << 10) | i;
    }
}

// ---------------- persistent level-parallel GRU (mma.sync, 512 thr) ------------
__device__ __forceinline__ void grid_barrier() {
    __threadfence();
    __syncthreads();
    if (threadIdx.x == 0) {
        unsigned gen = *(volatile unsigned*)&g_bar_gen;
        if (atomicAdd(&g_bar_count, 1u) == (unsigned)gridDim.x - 1u) {
            g_bar_count = 0u;
            __threadfence();
            *(volatile unsigned*)&g_bar_gen = gen + 1u;
        } else {
            while (*(volatile unsigned*)&g_bar_gen == gen) { }
        }
        __threadfence();
    }
    __syncthreads();
}

// 16 warps; warp wid owns n-tiles {wid + 16*jj : jj=0..5}; n = 8*wid + 128*jj.
// Gate triplet for base col c = 8*wid + 128*jj (jj=0,1): cols c, c+256, c+512
// live in jj, jj+2, jj+4 of the SAME warp.
__global__ void __launch_bounds__(512, 1) seq_kernel(const int* __restrict__ lpi,
                                                     const float* __restrict__ bhh,
                                                     float* __restrict__ out) {
    __shared__ __half sH[TG * PITCH];
    __shared__ int sMeta[TG];
    __shared__ int sPar[TG];
    int tid = threadIdx.x;
    int wid = tid >> 5, lane = tid & 31;
    int gid = lane >> 2, tq = lane & 3;
    int maxd = g_maxd;

    uint32_t* dH = (uint32_t*)sH;

    int l7 = lane & 7, q = lane >> 3;
    uint32_t aoff = (((q & 1) * 8 + l7) * (PITCH/2) + (q >> 1) * 4) * 4;
    uint32_t sHA = smem_u32(sH);
    uint32_t ad[2];
    #pragma unroll
    for (int mt = 0; mt < 2; mt++)
        ad[mt] = sHA + (mt * 16) * (PITCH*2) + aoff;

    for (int r = 0; r <= maxd; r++) {
        int start = g_rptr[r];
        int cnt   = g_rptr[r+1] - start;
        int ngroups = (cnt + TG - 1) / TG;
        for (int g = blockIdx.x; g < ngroups; g += gridDim.x) {
            int t0 = start + g * TG;
            int tc = cnt - g * TG; if (tc > TG) tc = TG;
            if (tid < TG) {
                if (tid < tc) {
                    int s = g_sched[t0 + tid];
                    sMeta[tid] = s;
                    int b = s >> 10, i = s & 1023;
                    sPar[tid] = (i == 0) ? -1 : ((b << 10) | lpi[b*NN + i]);
                } else { sMeta[tid] = 0; sPar[tid] = -1; }
            }
            __syncthreads();
            // gather parents -> fp16 smem
            for (int idx = tid; idx < TG * 64; idx += 512) {
                int t = idx >> 6, k4 = idx & 63;
                int pr = sPar[t];
                float4 v;
                if (pr < 0) { v.x=v.y=v.z=v.w=0.f; }
                else        { v = ((const float4*)&g_h[(long)pr*HH])[k4]; }
                int o = t * (PITCH/2) + k4 * 2;
                dH[o]   = pack_h2(v.x, v.y);
                dH[o+1] = pack_h2(v.z, v.w);
            }
            __syncthreads();

            float C[2][6][4];
            #pragma unroll
            for (int mt = 0; mt < 2; mt++)
                #pragma unroll
                for (int jj = 0; jj < 6; jj++)
                    #pragma unroll
                    for (int qq = 0; qq < 4; qq++) C[mt][jj][qq] = 0.0f;

            #pragma unroll 2
            for (int ks = 0; ks < 16; ks++) {
                uint32_t aF[2][4];
                #pragma unroll
                for (int mt = 0; mt < 2; mt++) ldsm4(ad[mt] + ks * 32, aF[mt]);
                uint4 bw[6];
                #pragma unroll
                for (int jj = 0; jj < 6; jj++) {
                    int n = 8 * wid + 128 * jj + gid;
                    bw[jj] = g_whh_p[n * 64 + ks * 4 + tq];
                }
                // all hi-term MMAs first (12 independent accumulators), then lo
                #pragma unroll
                for (int jj = 0; jj < 6; jj++)
                    #pragma unroll
                    for (int mt = 0; mt < 2; mt++)
                        mma16816(C[mt][jj], aF[mt][0], aF[mt][1], aF[mt][2], aF[mt][3],
                                 bw[jj].x, bw[jj].y);
                #pragma unroll
                for (int jj = 0; jj < 6; jj++)
                    #pragma unroll
                    for (int mt = 0; mt < 2; mt++)
                        mma16816(C[mt][jj], aF[mt][0], aF[mt][1], aF[mt][2], aF[mt][3],
                                 bw[jj].z, bw[jj].w);
            }

            // fused GRU epilogue
            #pragma unroll
            for (int jj = 0; jj < 2; jj++) {
                int cp = 8 * wid + 128 * jj + tq * 2;     // base col in [0,256)
                float2 br = *(const float2*)(bhh + cp);
                float2 bz = *(const float2*)(bhh + 256 + cp);
                float2 bn = *(const float2*)(bhh + 512 + cp);
                #pragma unroll
                for (int mt = 0; mt < 2; mt++) {
                    #pragma unroll
                    for (int rh = 0; rh < 2; rh++) {
                        int lr = mt * 16 + gid + rh * 8;
                        if (lr >= tc) continue;
                        float cr0 = C[mt][jj][rh*2],   cr1 = C[mt][jj][rh*2+1];
                        float cz0 = C[mt][jj+2][rh*2], cz1 = C[mt][jj+2][rh*2+1];
                        float cn0 = C[mt][jj+4][rh*2], cn1 = C[mt][jj+4][rh*2+1];
                        int s = sMeta[lr];
                        long row = (long)s;
                        int b = s >> 10, i = s & 1023;
                        const float* gp = g_gi + row * G3;
                        float2 gr = *(const float2*)(gp + cp);
                        float2 gz = *(const float2*)(gp + 256 + cp);
                        float2 gn = *(const float2*)(gp + 512 + cp);
                        int pr = sPar[lr];
                        float hp0, hp1;
                        if (pr < 0) { hp0 = 0.f; hp1 = 0.f; }
                        else {
                            float2 hv = *(const float2*)(g_h + (long)pr * HH + cp);
                            hp0 = hv.x; hp1 = hv.y;
                        }
                        float rg0 = sigm(gr.x + cr0 + br.x);
                        float rg1 = sigm(gr.y + cr1 + br.y);
                        float zg0 = sigm(gz.x + cz0 + bz.x);
                        float zg1 = sigm(gz.y + cz1 + bz.y);
                        float ng0 = tanhf(gn.x + (cn0 + bn.x) * rg0);
                        float ng1 = tanhf(gn.y + (cn1 + bn.y) * rg1);
                        float h0 = (1.0f - zg0) * ng0 + zg0 * hp0;
                        float h1 = (1.0f - zg1) * ng1 + zg1 * hp1;
                        *(float2*)(g_h + row * HH + cp) = make_float2(h0, h1);
                        *(float2*)(out + ((long)(i*BB + b) * (DD+HH)) + DD + cp) = make_float2(h0, h1);
                    }
                }
            }
            __syncthreads();
        }
        grid_barrier();
    }
}

// ---------------- launch -------------------------------------------------------
extern "C" void kernel_launch(void* const* d_in, const int* in_sizes, int n_in,
                              void* d_out, int out_size) {
    const int*   node_types      = (const int*)  d_in[0];
    const int*   node_vals       = (const int*)  d_in[1];
    const int*   last_parent     = (const int*)  d_in[3];
    const int*   child_positions = (const int*)  d_in[4];
    const float* type_emb        = (const float*)d_in[5];
    const float* pos_table       = (const float*)d_in[6];
    const float* token_emb       = (const float*)d_in[7];
    const float* w_ih            = (const float*)d_in[8];
    const float* w_hh            = (const float*)d_in[9];
    const float* b_ih            = (const float*)d_in[10];
    const float* b_hh            = (const float*)d_in[11];
    float* out = (float*)d_out;

    cudaFuncSetAttribute(gi_mma_kernel, cudaFuncAttributeMaxDynamicSharedMemorySize, GI_SMEM);

    prep_kernel<<<192, 256>>>(w_ih, w_hh);
    embed_kernel<<<NB, 256>>>(node_types, node_vals, child_positions,
                              type_emb, pos_table, token_emb, out);
    gi_mma_kernel<<<NB/128, 512, GI_SMEM>>>(b_ih);
    sched1_kernel<<<BB, 256>>>(last_parent);
    sched2_kernel<<<1, 1024>>>();
    sched3_kernel<<<BB, 256>>>();
    seq_kernel<<<SEQ_CTAS, 512>>>(last_parent, b_hh, out);
}

// round 8
// speedup vs baseline: 5.2925x; 1.1089x over previous
#include <cuda_runtime.h>
#include <cuda_fp16.h>
#include <math.h>
#include <stdint.h>

// Problem constants
#define BB   64
#define NN   1024
#define DD   256
#define HH   256
#define G3   768            // 3*H
#define NB   (BB*NN)        // 65536 rows
#define TG   32             // rows per group in seq kernel
#define SEQ_CTAS 148
#define PITCH 264           // fp16 pitch for A smem tiles (132 u32; LDSM conflict-free)

// ---------------- scratch (device globals) ------------------------------------
__device__ float g_gi  [NB*G3];                 // input gates (192 MB)
__device__ float g_h   [NB*HH];                 // hidden states (64 MB)
__device__ __half g_x_h[NB*DD];                 // fp16 activations
// gi weights: hi-only frag pack [n][ks][tq] -> uint2 {hi0, hi1}
__device__ __align__(16) uint2 g_wih_h2[G3*64];
// seq weights: fp16 split pack [n][ks][tq] -> uint4 {hi0, hi1, lo0, lo1}
__device__ __align__(16) uint4 g_whh_p[G3*64];
__device__ unsigned short g_depth[NB];
__device__ int   g_cnt    [BB*NN];
__device__ int   g_rbstart[BB*NN];
__device__ int   g_rptr   [NN+1];
__device__ int   g_sched  [NB];
__device__ int   g_maxd;
__device__ unsigned g_bar_count = 0;
__device__ unsigned g_bar_gen   = 0;

// ---------------- helpers ------------------------------------------------------
// NOTE: non-volatile on purpose — pure op, lets ptxas software-pipeline/interleave.
__device__ __forceinline__ void mma16816(float* c,
        uint32_t a0, uint32_t a1, uint32_t a2, uint32_t a3,
        uint32_t b0, uint32_t b1) {
    asm("mma.sync.aligned.m16n8k16.row.col.f32.f16.f16.f32 "
        "{%0,%1,%2,%3}, {%4,%5,%6,%7}, {%8,%9}, {%0,%1,%2,%3};"
        : "+f"(c[0]), "+f"(c[1]), "+f"(c[2]), "+f"(c[3])
        : "r"(a0), "r"(a1), "r"(a2), "r"(a3), "r"(b0), "r"(b1));
}
__device__ __forceinline__ void ldsm4(uint32_t addr, uint32_t* r) {
    asm volatile("ldmatrix.sync.aligned.m8n8.x4.shared.b16 {%0,%1,%2,%3}, [%4];"
        : "=r"(r[0]), "=r"(r[1]), "=r"(r[2]), "=r"(r[3]) : "r"(addr));
}
__device__ __forceinline__ uint32_t smem_u32(const void* p) {
    uint32_t a;
    asm("{ .reg .u64 t; cvta.to.shared.u64 t, %1; cvt.u32.u64 %0, t; }" : "=r"(a) : "l"(p));
    return a;
}
__device__ __forceinline__ uint32_t pack_h2(float x, float y) {
    __half2 h = __floats2half2_rn(x, y);
    return *reinterpret_cast<uint32_t*>(&h);
}
__device__ __forceinline__ float sigm(float x) { return 1.0f / (1.0f + expf(-x)); }

// ---------------- prep: frag-pack weights --------------------------------------
__global__ void prep_kernel(const float* __restrict__ wih,
                            const float* __restrict__ whh) {
    int e = blockIdx.x * blockDim.x + threadIdx.x;   // 0..49151
    if (e == 0) g_maxd = 0;
    if (e >= G3*64) return;
    int n  = e >> 6;
    int r  = e & 63;
    int ks = r >> 2, tq = r & 3;
    int p  = ks*8 + tq;
    int k0 = 2*p;
    // gi weights: hi only
    {
        float f0 = wih[n*256 + k0],     f1 = wih[n*256 + k0 + 1];
        float f2 = wih[n*256 + k0 + 8], f3 = wih[n*256 + k0 + 9];
        uint2 v;
        v.x = pack_h2(f0, f1);
        v.y = pack_h2(f2, f3);
        g_wih_h2[e] = v;
    }
    // seq weights: hi/lo split
    {
        float f0 = whh[n*256 + k0],     f1 = whh[n*256 + k0 + 1];
        float f2 = whh[n*256 + k0 + 8], f3 = whh[n*256 + k0 + 9];
        __half h0 = __float2half(f0), h1 = __float2half(f1);
        __half h2 = __float2half(f2), h3 = __float2half(f3);
        uint4 v;
        v.x = pack_h2(__half2float(h0), __half2float(h1));
        v.y = pack_h2(__half2float(h2), __half2float(h3));
        v.z = pack_h2(f0 - __half2float(h0), f1 - __half2float(h1));
        v.w = pack_h2(f2 - __half2float(h2), f3 - __half2float(h3));
        g_whh_p[e] = v;
    }
}

// ---------------- embeddings + first half of output ----------------------------
__global__ void embed_kernel(const int* __restrict__ node_types,
                             const int* __restrict__ node_vals,
                             const int* __restrict__ child_positions,
                             const float* __restrict__ type_emb,
                             const float* __restrict__ pos_table,
                             const float* __restrict__ token_emb,
                             float* __restrict__ out) {
    int id  = blockIdx.x;
    int tid = threadIdx.x;
    int b = id >> 10, n = id & 1023;
    int tt = node_types[id];
    int cp = child_positions[id];
    int v0 = node_vals[2*id];
    int v1 = node_vals[2*id + 1];
    float x = type_emb[tt*DD + tid] * 4.0f + pos_table[cp*DD + tid] * 0.25f;
    float tok = token_emb[v0*DD + tid] + token_emb[v1*DD + tid];
    g_x_h[id*DD + tid] = __float2half(x);
    out[((n*BB + b) * (DD+HH)) + tid] = x + tok * 2.0f;
}

// ---------------- GI GEMM: 512 threads, M=128/CTA, 3 N-chunks, single fp16 term
#define GI_SMEM (128 * PITCH * 2)   // fp16 A tile, bytes

__global__ void __launch_bounds__(512, 1) gi_mma_kernel(const float* __restrict__ bih) {
    extern __shared__ __half sA[];              // [128][PITCH]
    int tid = threadIdx.x;
    int wid = tid >> 5, lane = tid & 31;
    int gid = lane >> 2, tq = lane & 3;
    int wm = wid >> 3, wc = wid & 7;
    long row0 = (long)blockIdx.x * 128;

    // fill A: 128 rows x 128 u32
    {
        const uint32_t* src = (const uint32_t*)g_x_h + row0 * 128;
        uint32_t* dst = (uint32_t*)sA;
        for (int idx = tid; idx < 128 * 128; idx += 512) {
            int m = idx >> 7, j = idx & 127;
            dst[m * (PITCH/2) + j] = src[idx];
        }
    }
    __syncthreads();

    int l7 = lane & 7, q = lane >> 3;
    uint32_t aoff = (((q & 1) * 8 + l7) * (PITCH/2) + (q >> 1) * 4) * 4;
    uint32_t sAA = smem_u32(sA);
    uint32_t ad[4];
    #pragma unroll
    for (int mt = 0; mt < 4; mt++)
        ad[mt] = sAA + (wm * 64 + mt * 16) * (PITCH*2) + aoff;

    for (int c = 0; c < 3; c++) {
        float C[4][4][4];
        #pragma unroll
        for (int mt = 0; mt < 4; mt++)
            #pragma unroll
            for (int nt = 0; nt < 4; nt++)
                #pragma unroll
                for (int qq = 0; qq < 4; qq++) C[mt][nt][qq] = 0.0f;

        #pragma unroll 2
        for (int ks = 0; ks < 16; ks++) {
            uint32_t aF[4][4];
            #pragma unroll
            for (int mt = 0; mt < 4; mt++) ldsm4(ad[mt] + ks * 32, aF[mt]);
            uint2 bw[4];
            #pragma unroll
            for (int nt = 0; nt < 4; nt++) {
                int n = c * 256 + wc * 32 + nt * 8 + gid;
                bw[nt] = g_wih_h2[n * 64 + ks * 4 + tq];
            }
            #pragma unroll
            for (int nt = 0; nt < 4; nt++)
                #pragma unroll
                for (int mt = 0; mt < 4; mt++)
                    mma16816(C[mt][nt], aF[mt][0], aF[mt][1], aF[mt][2], aF[mt][3],
                             bw[nt].x, bw[nt].y);
        }
        // epilogue: add bias, store fp32
        #pragma unroll
        for (int mt = 0; mt < 4; mt++) {
            long r = row0 + wm * 64 + mt * 16 + gid;
            #pragma unroll
            for (int nt = 0; nt < 4; nt++) {
                int col = c * 256 + wc * 32 + nt * 8 + tq * 2;
                float2 bv = *(const float2*)(bih + col);
                float2 v0 = make_float2(C[mt][nt][0] + bv.x, C[mt][nt][1] + bv.y);
                float2 v1 = make_float2(C[mt][nt][2] + bv.x, C[mt][nt][3] + bv.y);
                *(float2*)(g_gi + r * G3 + col)       = v0;
                *(float2*)(g_gi + (r + 8) * G3 + col) = v1;
            }
        }
    }
}

// ---------------- scheduler S1: parallel pointer-doubling depths ---------------
__global__ void __launch_bounds__(256) sched1_kernel(const int* __restrict__ lpi) {
    __shared__ int            jb[NN];
    __shared__ unsigned short db[NN];
    __shared__ int            scnt[NN];
    __shared__ int            smax;
    int b = blockIdx.x, tid = threadIdx.x;
    if (tid == 0) smax = 0;
    for (int i = tid; i < NN; i += 256) {
        jb[i] = (i == 0) ? 0 : lpi[b*NN + i];
        db[i] = (i == 0) ? 0 : 1;
        scnt[i] = 0;
    }
    __syncthreads();
    #pragma unroll 1
    for (int s = 0; s < 10; s++) {
        int nd[4], nj[4];
        #pragma unroll
        for (int u = 0; u < 4; u++) {
            int i = tid + u * 256;
            int j = jb[i];
            nd[u] = db[i] + db[j];
            nj[u] = jb[j];
        }
        __syncthreads();
        #pragma unroll
        for (int u = 0; u < 4; u++) {
            int i = tid + u * 256;
            db[i] = (unsigned short)nd[u];
            jb[i] = nj[u];
        }
        __syncthreads();
    }
    int lm = 0;
    for (int i = tid; i < NN; i += 256) {
        atomicAdd(&scnt[db[i]], 1);
        lm = max(lm, (int)db[i]);
    }
    atomicMax(&smax, lm);
    __syncthreads();
    if (tid == 0) atomicMax(&g_maxd, smax);
    for (int i = tid; i < NN; i += 256) {
        g_depth[b*NN + i] = db[i];
        g_cnt  [b*NN + i] = scnt[i];
    }
}

// ---------------- scheduler S2 -------------------------------------------------
__global__ void __launch_bounds__(1024) sched2_kernel() {
    __shared__ int stot[NN];
    __shared__ int srptr[NN+1];
    int r = threadIdx.x;
    int s = 0;
    for (int b = 0; b < BB; b++) {
        g_rbstart[b*NN + r] = s;
        s += g_cnt[b*NN + r];
    }
    stot[r] = s;
    __syncthreads();
    if (r == 0) {
        int acc = 0;
        for (int i = 0; i < NN; i++) { srptr[i] = acc; acc += stot[i]; }
        srptr[NN] = acc;
    }
    __syncthreads();
    for (int b = 0; b < BB; b++) g_rbstart[b*NN + r] += srptr[r];
    g_rptr[r] = srptr[r];
    if (r == 0) g_rptr[NN] = srptr[NN];
}

// ---------------- scheduler S3: parallel scatter -------------------------------
__global__ void __launch_bounds__(256) sched3_kernel() {
    __shared__ int scur[NN];
    int b = blockIdx.x, tid = threadIdx.x;
    for (int i = tid; i < NN; i += 256) scur[i] = g_rbstart[b*NN + i];
    __syncthreads();
    for (int i = tid; i < NN; i += 256) {
        int d = g_depth[b*NN + i];
        int pos = atomicAdd(&scur[d], 1);
        g_sched[pos] = (b << 10) | i;
    }
}

// ---------------- persistent level-parallel GRU (mma.sync, 512 thr) ------------
__device__ __forceinline__ void grid_barrier() {
    __threadfence();
    __syncthreads();
    if (threadIdx.x == 0) {
        unsigned gen = *(volatile unsigned*)&g_bar_gen;
        if (atomicAdd(&g_bar_count, 1u) == (unsigned)gridDim.x - 1u) {
            g_bar_count = 0u;
            __threadfence();
            *(volatile unsigned*)&g_bar_gen = gen + 1u;
        } else {
            while (*(volatile unsigned*)&g_bar_gen == gen) { }
        }
        __threadfence();
    }
    __syncthreads();
}

// Column-split groups: each (rows-group, half) pair is one work unit.
// Half h owns output cols [h*128, h*128+128). Warp wid (0..15) owns base col
// cp = h*128 + 8*wid; gate triplet n-tiles: n = jj*256 + h*128 + 8*wid, jj=0..2.
__global__ void __launch_bounds__(512, 1) seq_kernel(const int* __restrict__ lpi,
                                                     const float* __restrict__ bhh,
                                                     float* __restrict__ out) {
    __shared__ __half sH[TG * PITCH];
    __shared__ int sMeta[TG];
    __shared__ int sPar[TG];
    int tid = threadIdx.x;
    int wid = tid >> 5, lane = tid & 31;
    int gid = lane >> 2, tq = lane & 3;
    int maxd = g_maxd;

    uint32_t* dH = (uint32_t*)sH;

    int l7 = lane & 7, q = lane >> 3;
    uint32_t aoff = (((q & 1) * 8 + l7) * (PITCH/2) + (q >> 1) * 4) * 4;
    uint32_t sHA = smem_u32(sH);
    uint32_t ad[2];
    #pragma unroll
    for (int mt = 0; mt < 2; mt++)
        ad[mt] = sHA + (mt * 16) * (PITCH*2) + aoff;

    for (int r = 0; r <= maxd; r++) {
        int start = g_rptr[r];
        int cnt   = g_rptr[r+1] - start;
        int nrow_groups = (cnt + TG - 1) / TG;
        int nunits = nrow_groups * 2;              // column-split x2
        for (int u = blockIdx.x; u < nunits; u += gridDim.x) {
            int gidx = u >> 1;
            int half = u & 1;
            int t0 = start + gidx * TG;
            int tc = cnt - gidx * TG; if (tc > TG) tc = TG;
            if (tid < TG) {
                if (tid < tc) {
                    int s = g_sched[t0 + tid];
                    sMeta[tid] = s;
                    int b = s >> 10, i = s & 1023;
                    sPar[tid] = (i == 0) ? -1 : ((b << 10) | lpi[b*NN + i]);
                } else { sMeta[tid] = 0; sPar[tid] = -1; }
            }
            __syncthreads();
            // gather parents -> fp16 smem (full K range; both halves duplicate)
            for (int idx = tid; idx < TG * 64; idx += 512) {
                int t = idx >> 6, k4 = idx & 63;
                int pr = sPar[t];
                float4 v;
                if (pr < 0) { v.x=v.y=v.z=v.w=0.f; }
                else        { v = ((const float4*)&g_h[(long)pr*HH])[k4]; }
                int o = t * (PITCH/2) + k4 * 2;
                dH[o]   = pack_h2(v.x, v.y);
                dH[o+1] = pack_h2(v.z, v.w);
            }
            __syncthreads();

            float C[2][3][4];
            #pragma unroll
            for (int mt = 0; mt < 2; mt++)
                #pragma unroll
                for (int jj = 0; jj < 3; jj++)
                    #pragma unroll
                    for (int qq = 0; qq < 4; qq++) C[mt][jj][qq] = 0.0f;

            int nbase = half * 128 + 8 * wid;
            #pragma unroll 2
            for (int ks = 0; ks < 16; ks++) {
                uint32_t aF[2][4];
                #pragma unroll
                for (int mt = 0; mt < 2; mt++) ldsm4(ad[mt] + ks * 32, aF[mt]);
                uint4 bw[3];
                #pragma unroll
                for (int jj = 0; jj < 3; jj++) {
                    int n = jj * 256 + nbase + gid;
                    bw[jj] = g_whh_p[n * 64 + ks * 4 + tq];
                }
                // hi terms first across 6 independent accumulators, then lo
                #pragma unroll
                for (int jj = 0; jj < 3; jj++)
                    #pragma unroll
                    for (int mt = 0; mt < 2; mt++)
                        mma16816(C[mt][jj], aF[mt][0], aF[mt][1], aF[mt][2], aF[mt][3],
                                 bw[jj].x, bw[jj].y);
                #pragma unroll
                for (int jj = 0; jj < 3; jj++)
                    #pragma unroll
                    for (int mt = 0; mt < 2; mt++)
                        mma16816(C[mt][jj], aF[mt][0], aF[mt][1], aF[mt][2], aF[mt][3],
                                 bw[jj].z, bw[jj].w);
            }

            // fused GRU epilogue: one base col per warp
            {
                int cp = nbase + tq * 2;              // output col in [0,256)
                float2 br = *(const float2*)(bhh + cp);
                float2 bz = *(const float2*)(bhh + 256 + cp);
                float2 bn = *(const float2*)(bhh + 512 + cp);
                #pragma unroll
                for (int mt = 0; mt < 2; mt++) {
                    #pragma unroll
                    for (int rh = 0; rh < 2; rh++) {
                        int lr = mt * 16 + gid + rh * 8;
                        if (lr >= tc) continue;
                        float cr0 = C[mt][0][rh*2], cr1 = C[mt][0][rh*2+1];
                        float cz0 = C[mt][1][rh*2], cz1 = C[mt][1][rh*2+1];
                        float cn0 = C[mt][2][rh*2], cn1 = C[mt][2][rh*2+1];
                        int s = sMeta[lr];
                        long row = (long)s;
                        int b = s >> 10, i = s & 1023;
                        const float* gp = g_gi + row * G3;
                        float2 gr = *(const float2*)(gp + cp);
                        float2 gz = *(const float2*)(gp + 256 + cp);
                        float2 gn = *(const float2*)(gp + 512 + cp);
                        int pr = sPar[lr];
                        float hp0, hp1;
                        if (pr < 0) { hp0 = 0.f; hp1 = 0.f; }
                        else {
                            float2 hv = *(const float2*)(g_h + (long)pr * HH + cp);
                            hp0 = hv.x; hp1 = hv.y;
                        }
                        float rg0 = sigm(gr.x + cr0 + br.x);
                        float rg1 = sigm(gr.y + cr1 + br.y);
                        float zg0 = sigm(gz.x + cz0 + bz.x);
                        float zg1 = sigm(gz.y + cz1 + bz.y);
                        float ng0 = tanhf(gn.x + (cn0 + bn.x) * rg0);
                        float ng1 = tanhf(gn.y + (cn1 + bn.y) * rg1);
                        float h0 = (1.0f - zg0) * ng0 + zg0 * hp0;
                        float h1 = (1.0f - zg1) * ng1 + zg1 * hp1;
                        *(float2*)(g_h + row * HH + cp) = make_float2(h0, h1);
                        *(float2*)(out + ((long)(i*BB + b) * (DD+HH)) + DD + cp) = make_float2(h0, h1);
                    }
                }
            }
            __syncthreads();
        }
        grid_barrier();
    }
}

// ---------------- launch -------------------------------------------------------
extern "C" void kernel_launch(void* const* d_in, const int* in_sizes, int n_in,
                              void* d_out, int out_size) {
    const int*   node_types      = (const int*)  d_in[0];
    const int*   node_vals       = (const int*)  d_in[1];
    const int*   last_parent     = (const int*)  d_in[3];
    const int*   child_positions = (const int*)  d_in[4];
    const float* type_emb        = (const float*)d_in[5];
    const float* pos_table       = (const float*)d_in[6];
    const float* token_emb       = (const float*)d_in[7];
    const float* w_ih            = (const float*)d_in[8];
    const float* w_hh            = (const float*)d_in[9];
    const float* b_ih            = (const float*)d_in[10];
    const float* b_hh            = (const float*)d_in[11];
    float* out = (float*)d_out;

    cudaFuncSetAttribute(gi_mma_kernel, cudaFuncAttributeMaxDynamicSharedMemorySize, GI_SMEM);

    prep_kernel<<<192, 256>>>(w_ih, w_hh);
    embed_kernel<<<NB, 256>>>(node_types, node_vals, child_positions,
                              type_emb, pos_table, token_emb, out);
    gi_mma_kernel<<<NB/128, 512, GI_SMEM>>>(b_ih);
    sched1_kernel<<<BB, 256>>>(last_parent);
    sched2_kernel<<<1, 1024>>>();
    sched3_kernel<<<BB, 256>>>();
    seq_kernel<<<SEQ_CTAS, 512>>>(last_parent, b_hh, out);
}